// round 4
// baseline (speedup 1.0000x reference)
#include <cuda_runtime.h>
#include <cuda_fp16.h>

#define L 4096
#define C 64
#define NB 4

// Scratch (device globals -- allocation in kernel_launch is forbidden).
__device__ float  g_M[NB][L * L];    // M (fp32); later reused for split-K partials
__device__ __half g_Eh[NB][L * L];   // normalized attn (fp16)
__device__ __half g_Sh[NB][L * L];   // S (fp16)

// ---- packed fp32x2 helpers ----
__device__ __forceinline__ unsigned long long pack2(float x, float y) {
    unsigned long long r;
    asm("mov.b64 %0, {%1, %2};" : "=l"(r) : "f"(x), "f"(y));
    return r;
}
__device__ __forceinline__ void fma2(unsigned long long &d, unsigned long long a,
                                     unsigned long long b) {
    asm("fma.rn.f32x2 %0, %1, %2, %3;" : "=l"(d) : "l"(a), "l"(b), "l"(d));
}

// ============================================================
// K1: M[p,l] = sum_c f[c,p]*b[c,l]   128x128 tile, 8x8/thread
// ============================================================
__global__ __launch_bounds__(256) void k_gemm_M(const float *__restrict__ fin,
                                                const float *__restrict__ bin) {
    __shared__ float As[32][128];  // [c][p]
    __shared__ float Bs[32][128];  // [c][l]
    const int bt = blockIdx.z;
    const int p0 = blockIdx.y << 7;
    const int l0 = blockIdx.x << 7;
    const float *fb = fin + bt * (C * L);
    const float *bb = bin + bt * (C * L);
    const int tid = threadIdx.x;
    const int tx = tid & 15, ty = tid >> 4;
    unsigned long long acc[8][4] = {};

    for (int kt = 0; kt < 2; kt++) {
        __syncthreads();
#pragma unroll
        for (int i = 0; i < 4; i++) {
            int idx = tid + (i << 8);          // float4 index, 1024 total
            int c = idx >> 5, x4 = idx & 31;
            *(float4 *)&As[c][x4 << 2] =
                *(const float4 *)&fb[(kt * 32 + c) * L + p0 + (x4 << 2)];
            *(float4 *)&Bs[c][x4 << 2] =
                *(const float4 *)&bb[(kt * 32 + c) * L + l0 + (x4 << 2)];
        }
        __syncthreads();
#pragma unroll 8
        for (int c = 0; c < 32; c++) {
            float4 a0 = *(const float4 *)&As[c][ty << 3];
            float4 a1 = *(const float4 *)&As[c][(ty << 3) + 4];
            // conflict-free: two 64-halves, 16B stride across the phase
            ulonglong2 b0 = *(const ulonglong2 *)&Bs[c][tx << 2];
            ulonglong2 b1 = *(const ulonglong2 *)&Bs[c][64 + (tx << 2)];
            unsigned long long ap[8];
            ap[0] = pack2(a0.x, a0.x); ap[1] = pack2(a0.y, a0.y);
            ap[2] = pack2(a0.z, a0.z); ap[3] = pack2(a0.w, a0.w);
            ap[4] = pack2(a1.x, a1.x); ap[5] = pack2(a1.y, a1.y);
            ap[6] = pack2(a1.z, a1.z); ap[7] = pack2(a1.w, a1.w);
#pragma unroll
            for (int i = 0; i < 8; i++) {
                fma2(acc[i][0], ap[i], b0.x);
                fma2(acc[i][1], ap[i], b0.y);
                fma2(acc[i][2], ap[i], b1.x);
                fma2(acc[i][3], ap[i], b1.y);
            }
        }
    }
    float *out = g_M[bt];
#pragma unroll
    for (int i = 0; i < 8; i++) {
        const int row = p0 + (ty << 3) + i;
        ulonglong2 v0; v0.x = acc[i][0]; v0.y = acc[i][1];
        ulonglong2 v1; v1.x = acc[i][2]; v1.y = acc[i][3];
        *(ulonglong2 *)&out[row * L + l0 + (tx << 2)] = v0;
        *(ulonglong2 *)&out[row * L + l0 + 64 + (tx << 2)] = v1;
    }
}

// ============================================================
// K2: scores[p,l] = sum_d valid M[p+d,l+d]; row softmax;
// writes NORMALIZED attn (e * 1/rowsum) as fp16.
// ============================================================
__global__ __launch_bounds__(256) void k_score_softmax() {
    const int bt = blockIdx.y;
    const int p = blockIdx.x;
    const int py = p >> 6, px = p & 63;
    const float *__restrict__ M = g_M[bt];
    const int t = threadIdx.x;
    __shared__ float redA[8], redB[8];

    float s[16];
#pragma unroll
    for (int j = 0; j < 8; j++) {
        const int l = (j << 9) + (t << 1);
        const int ly = l >> 6, lx = l & 63;   // lx even; element 1 is lx+1 (same ly)
        float a0 = 0.f, a1 = 0.f;
#pragma unroll
        for (int dy = -1; dy <= 1; dy++) {
            if ((unsigned)(py + dy) >= 64u || (unsigned)(ly + dy) >= 64u) continue;
#pragma unroll
            for (int dx = -1; dx <= 1; dx++) {
                if ((unsigned)(px + dx) >= 64u) continue;
                const int off = dy * 64 + dx;
                const float *base = &M[(p + off) * L + l + off];
                if ((unsigned)(lx + dx) < 64u) a0 += base[0];
                if ((unsigned)(lx + 1 + dx) < 64u) a1 += base[1];
            }
        }
        s[2 * j] = a0;
        s[2 * j + 1] = a1;
    }
    float m = s[0];
#pragma unroll
    for (int k = 1; k < 16; k++) m = fmaxf(m, s[k]);
#pragma unroll
    for (int o = 16; o; o >>= 1) m = fmaxf(m, __shfl_xor_sync(0xffffffffu, m, o));
    if ((t & 31) == 0) redA[t >> 5] = m;
    __syncthreads();
    float rowmax = redA[0];
#pragma unroll
    for (int i = 1; i < 8; i++) rowmax = fmaxf(rowmax, redA[i]);

    float sum = 0.f;
#pragma unroll
    for (int k = 0; k < 16; k++) {
        float e = __expf(10.f * (s[k] - rowmax));
        s[k] = e;
        sum += e;
    }
#pragma unroll
    for (int o = 16; o; o >>= 1) sum += __shfl_xor_sync(0xffffffffu, sum, o);
    if ((t & 31) == 0) redB[t >> 5] = sum;
    __syncthreads();
    float tot = redB[0];
#pragma unroll
    for (int i = 1; i < 8; i++) tot += redB[i];
    const float rinv = 1.f / tot;

    __half2 *E2 = (__half2 *)(g_Eh[bt] + p * L);
#pragma unroll
    for (int j = 0; j < 8; j++)
        E2[(j << 8) + t] = __floats2half2_rn(s[2 * j] * rinv, s[2 * j + 1] * rinv);
}

// ============================================================
// K3: S[p,l] = (1/9) sum_d valid A[p+d,l+d]   (A fp16 -> S fp16)
// ============================================================
__global__ __launch_bounds__(256) void k_attn_S() {
    const int bt = blockIdx.y;
    const int p = blockIdx.x;
    const int py = p >> 6, px = p & 63;
    const __half *__restrict__ E = g_Eh[bt];
    const int t = threadIdx.x;

    __half2 *S2 = (__half2 *)(g_Sh[bt] + p * L);
#pragma unroll
    for (int j = 0; j < 8; j++) {
        const int l = (j << 9) + (t << 1);
        const int ly = l >> 6, lx = l & 63;
        float a0 = 0.f, a1 = 0.f;
#pragma unroll
        for (int dy = -1; dy <= 1; dy++) {
            if ((unsigned)(py + dy) >= 64u || (unsigned)(ly + dy) >= 64u) continue;
#pragma unroll
            for (int dx = -1; dx <= 1; dx++) {
                if ((unsigned)(px + dx) >= 64u) continue;
                const int off = dy * 64 + dx;
                const __half *base = &E[(p + off) * L + l + off];
                if ((unsigned)(lx + dx) < 64u) a0 += __half2float(base[0]);
                if ((unsigned)(lx + 1 + dx) < 64u) a1 += __half2float(base[1]);
            }
        }
        S2[(j << 8) + t] = __floats2half2_rn(a0 * (1.f / 9.f), a1 * (1.f / 9.f));
    }
}

// ============================================================
// K4: split-K GEMM  y[c,p] = sum_l S[p,l]*b[c,l]   (S fp16)
// grid (32 p-tiles, 8 k-splits, NB); 128 threads; 8x8/thread.
// Partials into g_M (free after K3).
// ============================================================
__global__ __launch_bounds__(128) void k_gemm_y(const float *__restrict__ bin) {
    __shared__ float Ss[32][132];  // [l][p]
    __shared__ float Bt[32][68];   // [l][c]
    const int bt = blockIdx.z;
    const int ks = blockIdx.y;
    const int p0 = blockIdx.x << 7;
    const __half *S = g_Sh[bt];
    const float *bb = bin + bt * (C * L);
    const int tid = threadIdx.x;
    const int tx = tid & 15, ty = tid >> 4;  // tx->p(8), ty->c(8)
    unsigned long long acc[8][4] = {};

    const int lt_end = (ks + 1) << 9;
    for (int lt = ks << 9; lt < lt_end; lt += 32) {
        __syncthreads();
        // S tile: thread tid owns p-row (p0+tid); 32 halves = 4x uint4
        {
            const __half *srow = &S[(p0 + tid) * L + lt];
#pragma unroll
            for (int q = 0; q < 4; q++) {
                uint4 v = *(const uint4 *)(srow + (q << 3));
                const __half2 *h = (const __half2 *)&v;
#pragma unroll
                for (int k = 0; k < 4; k++) {
                    float2 fv = __half22float2(h[k]);
                    Ss[(q << 3) + 2 * k][tid] = fv.x;
                    Ss[(q << 3) + 2 * k + 1][tid] = fv.y;
                }
            }
        }
        // b tile: thread (c = tid&63, half = tid>>6) loads 4 float4s
        {
            const int c = tid & 63, hf = tid >> 6;
            const float *brow = &bb[c * L + lt + (hf << 4)];
#pragma unroll
            for (int q = 0; q < 4; q++) {
                float4 v = *(const float4 *)(brow + (q << 2));
                const int lbase = (hf << 4) + (q << 2);
                Bt[lbase + 0][c] = v.x;
                Bt[lbase + 1][c] = v.y;
                Bt[lbase + 2][c] = v.z;
                Bt[lbase + 3][c] = v.w;
            }
        }
        __syncthreads();
#pragma unroll 8
        for (int l = 0; l < 32; l++) {
            ulonglong2 s0 = *(const ulonglong2 *)&Ss[l][tx << 2];
            ulonglong2 s1 = *(const ulonglong2 *)&Ss[l][64 + (tx << 2)];
            float4 b0 = *(const float4 *)&Bt[l][ty << 3];
            float4 b1 = *(const float4 *)&Bt[l][(ty << 3) + 4];
            unsigned long long ap[8];
            ap[0] = pack2(b0.x, b0.x); ap[1] = pack2(b0.y, b0.y);
            ap[2] = pack2(b0.z, b0.z); ap[3] = pack2(b0.w, b0.w);
            ap[4] = pack2(b1.x, b1.x); ap[5] = pack2(b1.y, b1.y);
            ap[6] = pack2(b1.z, b1.z); ap[7] = pack2(b1.w, b1.w);
#pragma unroll
            for (int ci = 0; ci < 8; ci++) {
                fma2(acc[ci][0], ap[ci], s0.x);
                fma2(acc[ci][1], ap[ci], s0.y);
                fma2(acc[ci][2], ap[ci], s1.x);
                fma2(acc[ci][3], ap[ci], s1.y);
            }
        }
    }
    float *part = (float *)g_M;
#pragma unroll
    for (int ci = 0; ci < 8; ci++) {
        const int c = (ty << 3) + ci;
        float *dst = part + (((bt << 3) + ks) * 64 + c) * L + p0;
        ulonglong2 v0; v0.x = acc[ci][0]; v0.y = acc[ci][1];
        ulonglong2 v1; v1.x = acc[ci][2]; v1.y = acc[ci][3];
        *(ulonglong2 *)(dst + (tx << 2)) = v0;
        *(ulonglong2 *)(dst + 64 + (tx << 2)) = v1;
    }
}

// reduce the 8 split-K partials into y
__global__ __launch_bounds__(256) void k_reduce_y(float *__restrict__ yout) {
    const int i = blockIdx.x * 256 + threadIdx.x;   // float4 index, 262144 total
    const int p4 = i & 1023;
    const int c = (i >> 10) & 63;
    const int bt = i >> 16;
    const float4 *part = (const float4 *)g_M;
    float4 s = make_float4(0.f, 0.f, 0.f, 0.f);
#pragma unroll
    for (int ks = 0; ks < 8; ks++) {
        float4 v = part[(((bt << 3) + ks) * 64 + c) * 1024 + p4];
        s.x += v.x; s.y += v.y; s.z += v.z; s.w += v.w;
    }
    ((float4 *)yout)[(bt * 64 + c) * 1024 + p4] = s;
}

// ============================================================
// K5: w output: w[b,l,c,i,j] = b[c, l + (i-1,j-1)]  (0 when OOB)
// ============================================================
__global__ __launch_bounds__(256) void k_wout(const float *__restrict__ bin,
                                              float *__restrict__ wout) {
    const int idx = blockIdx.x * 256 + threadIdx.x;
    const int j3 = idx % 9;
    const int c = (idx / 9) & 63;
    const int l = (idx / 576) & 4095;
    const int bt = idx / (576 * 4096);
    const int dy = j3 / 3 - 1, dx = j3 % 3 - 1;
    const int ly = l >> 6, lx = l & 63;
    float v = 0.f;
    if ((unsigned)(ly + dy) < 64u && (unsigned)(lx + dx) < 64u)
        v = bin[bt * (C * L) + c * L + l + dy * 64 + dx];
    wout[idx] = v;
}

extern "C" void kernel_launch(void *const *d_in, const int *in_sizes, int n_in,
                              void *d_out, int out_size) {
    const float *f = (const float *)d_in[0];
    const float *b = (const float *)d_in[1];
    float *out = (float *)d_out;

    k_gemm_M<<<dim3(32, 32, NB), 256>>>(f, b);
    k_score_softmax<<<dim3(L, NB), 256>>>();
    k_attn_S<<<dim3(L, NB), 256>>>();
    k_gemm_y<<<dim3(32, 8, NB), 128>>>(b);
    k_reduce_y<<<1024, 256>>>(out);
    k_wout<<<(NB * L * C * 9) / 256, 256>>>(b, out + NB * C * L);
}

// round 6
// speedup vs baseline: 1.2574x; 1.2574x over previous
#include <cuda_runtime.h>

#define L 4096
#define C 64
#define NB 4
#define GUARD (66 * 4096)
#define LL (L * L)

// Guarded scratch: [guard | NB batches | guard].  Guards are zeroed each call
// so unconditional (masked-to-zero) stencil loads never see NaN/Inf.
__device__ __align__(16) float g_Mbuf[2 * GUARD + NB * LL];  // M; later S
__device__ __align__(16) float g_Ebuf[2 * GUARD + NB * LL];  // E; later partials
__device__ float g_rinv[NB][L];

// ---- packed fp32x2 helpers ----
__device__ __forceinline__ unsigned long long pack2(float x, float y) {
    unsigned long long r;
    asm("mov.b64 %0, {%1, %2};" : "=l"(r) : "f"(x), "f"(y));
    return r;
}
__device__ __forceinline__ void fma2(unsigned long long &d, unsigned long long a,
                                     unsigned long long b) {
    asm("fma.rn.f32x2 %0, %1, %2, %3;" : "=l"(d) : "l"(a), "l"(b), "l"(d));
}

// zero the four guard regions (2 per buffer)
__global__ __launch_bounds__(256) void k_zero_guards() {
    const int i = blockIdx.x * 256 + threadIdx.x;   // float4 idx, < GUARD/4
    float4 z = make_float4(0.f, 0.f, 0.f, 0.f);
    ((float4 *)g_Mbuf)[i] = z;
    ((float4 *)(g_Mbuf + GUARD + NB * LL))[i] = z;
    ((float4 *)g_Ebuf)[i] = z;
    ((float4 *)(g_Ebuf + GUARD + NB * LL))[i] = z;
}

// One 9-point diagonal tap: 4 outputs from (1 or 2) aligned float4 loads.
// Reads M[(p+off)*L + (l+off)] = Mp + off*(L+1) + l.  off is compile-time,
// so the misaligned window is pure static register picking.
template <int DY, int DX>
__device__ __forceinline__ void tap(const float *__restrict__ Mp, int l, float m,
                                    float e0f, float e3f, float &a0, float &a1,
                                    float &a2, float &a3) {
    constexpr int off = DY * 64 + DX;
    constexpr int offset = off * (L + 1);   // diagonal: p-row shift + l shift
    constexpr int r = offset & 3;
    const float *src = Mp + l + (offset - r);
    float4 lo = *(const float4 *)src;
    float s0, s1, s2, s3;
    if (r == 0) {
        s0 = lo.x; s1 = lo.y; s2 = lo.z; s3 = lo.w;
    } else {
        float4 hi = *(const float4 *)(src + 4);
        if (r == 1)      { s0 = lo.y; s1 = lo.z; s2 = lo.w; s3 = hi.x; }
        else if (r == 2) { s0 = lo.z; s1 = lo.w; s2 = hi.x; s3 = hi.y; }
        else             { s0 = lo.w; s1 = hi.x; s2 = hi.y; s3 = hi.z; }
    }
    const float m0 = (DX == -1) ? m * e0f : m;
    const float m3 = (DX == 1) ? m * e3f : m;
    a0 = fmaf(m0, s0, a0);
    a1 = fmaf(m, s1, a1);
    a2 = fmaf(m, s2, a2);
    a3 = fmaf(m3, s3, a3);
}

// ============================================================
// K1: M[p,l] = sum_c f[c,p]*b[c,l]   128x128 tile, 8x8/thread
// ============================================================
__global__ __launch_bounds__(256) void k_gemm_M(const float *__restrict__ fin,
                                                const float *__restrict__ bin) {
    __shared__ float As[32][128];  // [c][p]
    __shared__ float Bs[32][128];  // [c][l]
    const int bt = blockIdx.z;
    const int p0 = blockIdx.y << 7;
    const int l0 = blockIdx.x << 7;
    const float *fb = fin + bt * (C * L);
    const float *bb = bin + bt * (C * L);
    const int tid = threadIdx.x;
    const int tx = tid & 15, ty = tid >> 4;
    unsigned long long acc[8][4] = {};

    for (int kt = 0; kt < 2; kt++) {
        __syncthreads();
#pragma unroll
        for (int i = 0; i < 4; i++) {
            int idx = tid + (i << 8);
            int c = idx >> 5, x4 = idx & 31;
            *(float4 *)&As[c][x4 << 2] =
                *(const float4 *)&fb[(kt * 32 + c) * L + p0 + (x4 << 2)];
            *(float4 *)&Bs[c][x4 << 2] =
                *(const float4 *)&bb[(kt * 32 + c) * L + l0 + (x4 << 2)];
        }
        __syncthreads();
#pragma unroll 8
        for (int c = 0; c < 32; c++) {
            float4 a0 = *(const float4 *)&As[c][ty << 3];
            float4 a1 = *(const float4 *)&As[c][(ty << 3) + 4];
            ulonglong2 b0 = *(const ulonglong2 *)&Bs[c][tx << 2];
            ulonglong2 b1 = *(const ulonglong2 *)&Bs[c][64 + (tx << 2)];
            unsigned long long ap[8];
            ap[0] = pack2(a0.x, a0.x); ap[1] = pack2(a0.y, a0.y);
            ap[2] = pack2(a0.z, a0.z); ap[3] = pack2(a0.w, a0.w);
            ap[4] = pack2(a1.x, a1.x); ap[5] = pack2(a1.y, a1.y);
            ap[6] = pack2(a1.z, a1.z); ap[7] = pack2(a1.w, a1.w);
#pragma unroll
            for (int i = 0; i < 8; i++) {
                fma2(acc[i][0], ap[i], b0.x);
                fma2(acc[i][1], ap[i], b0.y);
                fma2(acc[i][2], ap[i], b1.x);
                fma2(acc[i][3], ap[i], b1.y);
            }
        }
    }
    float *out = g_Mbuf + GUARD + (size_t)bt * LL;
#pragma unroll
    for (int i = 0; i < 8; i++) {
        const int row = p0 + (ty << 3) + i;
        ulonglong2 v0; v0.x = acc[i][0]; v0.y = acc[i][1];
        ulonglong2 v1; v1.x = acc[i][2]; v1.y = acc[i][3];
        *(ulonglong2 *)&out[row * L + l0 + (tx << 2)] = v0;
        *(ulonglong2 *)&out[row * L + l0 + 64 + (tx << 2)] = v1;
    }
}

// ============================================================
// K2: scores stencil (vectorized taps) + row softmax
// E = exp(10*(s-rowmax)) fp32, rinv stored separately.
// ============================================================
__global__ __launch_bounds__(256) void k_score_softmax() {
    const int bt = blockIdx.y;
    const int p = blockIdx.x;
    const int py = p >> 6, px = p & 63;
    const float *Mp = g_Mbuf + GUARD + (size_t)bt * LL + p * L;
    const int t = threadIdx.x;
    __shared__ float redA[8], redB[8];

    float pv[3][3];
#pragma unroll
    for (int dy = -1; dy <= 1; dy++)
#pragma unroll
        for (int dx = -1; dx <= 1; dx++)
            pv[dy + 1][dx + 1] =
                ((unsigned)(py + dy) < 64u && (unsigned)(px + dx) < 64u) ? 1.f : 0.f;
    const float e0f = ((t & 15) == 0) ? 0.f : 1.f;
    const float e3f = ((t & 15) == 15) ? 0.f : 1.f;

    float s[16];
#pragma unroll
    for (int j = 0; j < 4; j++) {
        const int gidx = (j << 8) + t;
        const int l = gidx << 2;
        const int ly = gidx >> 4;
        const float ym = ((unsigned)(ly - 1) < 64u) ? 1.f : 0.f;
        const float yp = ((unsigned)(ly + 1) < 64u) ? 1.f : 0.f;
        float a0 = 0.f, a1 = 0.f, a2 = 0.f, a3 = 0.f;
        tap<-1, -1>(Mp, l, pv[0][0] * ym, e0f, e3f, a0, a1, a2, a3);
        tap<-1, 0>(Mp, l, pv[0][1] * ym, e0f, e3f, a0, a1, a2, a3);
        tap<-1, 1>(Mp, l, pv[0][2] * ym, e0f, e3f, a0, a1, a2, a3);
        tap<0, -1>(Mp, l, pv[1][0], e0f, e3f, a0, a1, a2, a3);
        tap<0, 0>(Mp, l, pv[1][1], e0f, e3f, a0, a1, a2, a3);
        tap<0, 1>(Mp, l, pv[1][2], e0f, e3f, a0, a1, a2, a3);
        tap<1, -1>(Mp, l, pv[2][0] * yp, e0f, e3f, a0, a1, a2, a3);
        tap<1, 0>(Mp, l, pv[2][1] * yp, e0f, e3f, a0, a1, a2, a3);
        tap<1, 1>(Mp, l, pv[2][2] * yp, e0f, e3f, a0, a1, a2, a3);
        s[4 * j] = a0; s[4 * j + 1] = a1; s[4 * j + 2] = a2; s[4 * j + 3] = a3;
    }

    float m = s[0];
#pragma unroll
    for (int k = 1; k < 16; k++) m = fmaxf(m, s[k]);
#pragma unroll
    for (int o = 16; o; o >>= 1) m = fmaxf(m, __shfl_xor_sync(0xffffffffu, m, o));
    if ((t & 31) == 0) redA[t >> 5] = m;
    __syncthreads();
    float rowmax = redA[0];
#pragma unroll
    for (int i = 1; i < 8; i++) rowmax = fmaxf(rowmax, redA[i]);

    float sum = 0.f;
#pragma unroll
    for (int k = 0; k < 16; k++) {
        float e = __expf(10.f * (s[k] - rowmax));
        s[k] = e;
        sum += e;
    }
#pragma unroll
    for (int o = 16; o; o >>= 1) sum += __shfl_xor_sync(0xffffffffu, sum, o);
    if ((t & 31) == 0) redB[t >> 5] = sum;
    __syncthreads();

    float *E = g_Ebuf + GUARD + (size_t)bt * LL + p * L;
#pragma unroll
    for (int j = 0; j < 4; j++) {
        const int l = ((j << 8) + t) << 2;
        *(float4 *)&E[l] =
            make_float4(s[4 * j], s[4 * j + 1], s[4 * j + 2], s[4 * j + 3]);
    }

    if (t == 0) {
        float tot = 0.f;
#pragma unroll
        for (int i = 0; i < 8; i++) tot += redB[i];
        g_rinv[bt][p] = 1.f / tot;
    }
}

// ============================================================
// K3: S[p,l] = (1/9) sum_d E[p+d,l+d]*rinv[p+d]  -> g_Mbuf (fp32)
// per-tap multiplier = mask * rinv, folded into the tap FFMA.
// ============================================================
__global__ __launch_bounds__(256) void k_attn_S() {
    const int bt = blockIdx.y;
    const int p = blockIdx.x;
    const int py = p >> 6, px = p & 63;
    const float *Ep = g_Ebuf + GUARD + (size_t)bt * LL + p * L;
    const float *__restrict__ ri = g_rinv[bt];
    const int t = threadIdx.x;

    float rv[3][3];
#pragma unroll
    for (int dy = -1; dy <= 1; dy++)
#pragma unroll
        for (int dx = -1; dx <= 1; dx++) {
            bool ok = (unsigned)(py + dy) < 64u && (unsigned)(px + dx) < 64u;
            rv[dy + 1][dx + 1] = ok ? ri[p + dy * 64 + dx] : 0.f;
        }
    const float e0f = ((t & 15) == 0) ? 0.f : 1.f;
    const float e3f = ((t & 15) == 15) ? 0.f : 1.f;

    float *S = g_Mbuf + GUARD + (size_t)bt * LL + p * L;
#pragma unroll
    for (int j = 0; j < 4; j++) {
        const int gidx = (j << 8) + t;
        const int l = gidx << 2;
        const int ly = gidx >> 4;
        const float ym = ((unsigned)(ly - 1) < 64u) ? 1.f : 0.f;
        const float yp = ((unsigned)(ly + 1) < 64u) ? 1.f : 0.f;
        float a0 = 0.f, a1 = 0.f, a2 = 0.f, a3 = 0.f;
        tap<-1, -1>(Ep, l, rv[0][0] * ym, e0f, e3f, a0, a1, a2, a3);
        tap<-1, 0>(Ep, l, rv[0][1] * ym, e0f, e3f, a0, a1, a2, a3);
        tap<-1, 1>(Ep, l, rv[0][2] * ym, e0f, e3f, a0, a1, a2, a3);
        tap<0, -1>(Ep, l, rv[1][0], e0f, e3f, a0, a1, a2, a3);
        tap<0, 0>(Ep, l, rv[1][1], e0f, e3f, a0, a1, a2, a3);
        tap<0, 1>(Ep, l, rv[1][2], e0f, e3f, a0, a1, a2, a3);
        tap<1, -1>(Ep, l, rv[2][0] * yp, e0f, e3f, a0, a1, a2, a3);
        tap<1, 0>(Ep, l, rv[2][1] * yp, e0f, e3f, a0, a1, a2, a3);
        tap<1, 1>(Ep, l, rv[2][2] * yp, e0f, e3f, a0, a1, a2, a3);
        *(float4 *)&S[l] = make_float4(a0 * (1.f / 9.f), a1 * (1.f / 9.f),
                                       a2 * (1.f / 9.f), a3 * (1.f / 9.f));
    }
}

// ============================================================
// K4: split-K GEMM  y[c,p] = sum_l S[p,l]*b[c,l]
// grid (32 p-tiles, 8 k-splits, NB); 128 threads; 8x8/thread.
// Partials into g_Ebuf interior (E dead after K3).
// ============================================================
__global__ __launch_bounds__(128) void k_gemm_y(const float *__restrict__ bin) {
    __shared__ float Ss[32][132];  // [l][p]
    __shared__ float Bt[32][68];   // [l][c]
    const int bt = blockIdx.z;
    const int ks = blockIdx.y;
    const int p0 = blockIdx.x << 7;
    const float *S = g_Mbuf + GUARD + (size_t)bt * LL;
    const float *bb = bin + bt * (C * L);
    const int tid = threadIdx.x;
    const int tx = tid & 15, ty = tid >> 4;  // tx->p(8), ty->c(8)
    unsigned long long acc[8][4] = {};

    const int lt_end = (ks + 1) << 9;
    for (int lt = ks << 9; lt < lt_end; lt += 32) {
        __syncthreads();
#pragma unroll
        for (int i = 0; i < 8; i++) {
            int idx = tid + (i << 7);
            int r = idx >> 3, q4 = idx & 7;
            float4 v = *(const float4 *)&S[(p0 + r) * L + lt + (q4 << 2)];
            Ss[(q4 << 2) + 0][r] = v.x;
            Ss[(q4 << 2) + 1][r] = v.y;
            Ss[(q4 << 2) + 2][r] = v.z;
            Ss[(q4 << 2) + 3][r] = v.w;
        }
#pragma unroll
        for (int i = 0; i < 4; i++) {
            int idx = tid + (i << 7);
            int r = idx >> 3, q4 = idx & 7;
            float4 v = *(const float4 *)&bb[r * L + lt + (q4 << 2)];
            Bt[(q4 << 2) + 0][r] = v.x;
            Bt[(q4 << 2) + 1][r] = v.y;
            Bt[(q4 << 2) + 2][r] = v.z;
            Bt[(q4 << 2) + 3][r] = v.w;
        }
        __syncthreads();
#pragma unroll 8
        for (int l = 0; l < 32; l++) {
            ulonglong2 s0 = *(const ulonglong2 *)&Ss[l][tx << 2];
            ulonglong2 s1 = *(const ulonglong2 *)&Ss[l][64 + (tx << 2)];
            float4 b0 = *(const float4 *)&Bt[l][ty << 3];
            float4 b1 = *(const float4 *)&Bt[l][(ty << 3) + 4];
            unsigned long long ap[8];
            ap[0] = pack2(b0.x, b0.x); ap[1] = pack2(b0.y, b0.y);
            ap[2] = pack2(b0.z, b0.z); ap[3] = pack2(b0.w, b0.w);
            ap[4] = pack2(b1.x, b1.x); ap[5] = pack2(b1.y, b1.y);
            ap[6] = pack2(b1.z, b1.z); ap[7] = pack2(b1.w, b1.w);
#pragma unroll
            for (int ci = 0; ci < 8; ci++) {
                fma2(acc[ci][0], ap[ci], s0.x);
                fma2(acc[ci][1], ap[ci], s0.y);
                fma2(acc[ci][2], ap[ci], s1.x);
                fma2(acc[ci][3], ap[ci], s1.y);
            }
        }
    }
    float *part = g_Ebuf + GUARD;
#pragma unroll
    for (int ci = 0; ci < 8; ci++) {
        const int c = (ty << 3) + ci;
        float *dst = part + ((size_t)((bt << 3) + ks) * 64 + c) * L + p0;
        ulonglong2 v0; v0.x = acc[ci][0]; v0.y = acc[ci][1];
        ulonglong2 v1; v1.x = acc[ci][2]; v1.y = acc[ci][3];
        *(ulonglong2 *)(dst + (tx << 2)) = v0;
        *(ulonglong2 *)(dst + 64 + (tx << 2)) = v1;
    }
}

// reduce the 8 split-K partials into y
__global__ __launch_bounds__(256) void k_reduce_y(float *__restrict__ yout) {
    const int i = blockIdx.x * 256 + threadIdx.x;   // float4 idx, 262144 total
    const int p4 = i & 1023;
    const int c = (i >> 10) & 63;
    const int bt = i >> 16;
    const float4 *part = (const float4 *)(g_Ebuf + GUARD);
    float4 s = make_float4(0.f, 0.f, 0.f, 0.f);
#pragma unroll
    for (int ks = 0; ks < 8; ks++) {
        float4 v = part[((size_t)((bt << 3) + ks) * 64 + c) * 1024 + p4];
        s.x += v.x; s.y += v.y; s.z += v.z; s.w += v.w;
    }
    ((float4 *)yout)[(bt * 64 + c) * 1024 + p4] = s;
}

// ============================================================
// K5: w output: w[b,l,c,i,j] = b[c, l + (i-1,j-1)]  (0 when OOB)
// ============================================================
__global__ __launch_bounds__(256) void k_wout(const float *__restrict__ bin,
                                              float *__restrict__ wout) {
    const int idx = blockIdx.x * 256 + threadIdx.x;
    const int j3 = idx % 9;
    const int c = (idx / 9) & 63;
    const int l = (idx / 576) & 4095;
    const int bt = idx / (576 * 4096);
    const int dy = j3 / 3 - 1, dx = j3 % 3 - 1;
    const int ly = l >> 6, lx = l & 63;
    float v = 0.f;
    if ((unsigned)(ly + dy) < 64u && (unsigned)(lx + dx) < 64u)
        v = bin[bt * (C * L) + c * L + l + dy * 64 + dx];
    wout[idx] = v;
}

extern "C" void kernel_launch(void *const *d_in, const int *in_sizes, int n_in,
                              void *d_out, int out_size) {
    const float *f = (const float *)d_in[0];
    const float *b = (const float *)d_in[1];
    float *out = (float *)d_out;

    k_zero_guards<<<GUARD / 4 / 256, 256>>>();
    k_gemm_M<<<dim3(32, 32, NB), 256>>>(f, b);
    k_score_softmax<<<dim3(L, NB), 256>>>();
    k_attn_S<<<dim3(L, NB), 256>>>();
    k_gemm_y<<<dim3(32, 8, NB), 128>>>(b);
    k_reduce_y<<<1024, 256>>>(out);
    k_wout<<<(NB * L * C * 9) / 256, 256>>>(b, out + NB * C * L);
}

// round 7
// speedup vs baseline: 1.2883x; 1.0246x over previous
#include <cuda_runtime.h>
#include <cuda_fp16.h>

#define L 4096
#define C 64
#define NB 4
#define GUARD (66 * 4096)
#define LL (L * L)

// Guarded scratch.  Guards are zeroed each call so unconditional
// (masked-to-zero) stencil loads never see NaN/Inf.
__device__ __align__(16) float  g_Mbuf[2 * GUARD + NB * LL];  // M; later S (fp32)
__device__ __align__(16) __half g_Eh[2 * GUARD + NB * LL];    // E (fp16)
__device__ __align__(16) float  g_part[NB * 8 * C * L];       // split-K partials
__device__ float g_rinv[NB][L];

// ---- packed fp32x2 helpers ----
__device__ __forceinline__ unsigned long long pack2(float x, float y) {
    unsigned long long r;
    asm("mov.b64 %0, {%1, %2};" : "=l"(r) : "f"(x), "f"(y));
    return r;
}
__device__ __forceinline__ void fma2(unsigned long long &d, unsigned long long a,
                                     unsigned long long b) {
    asm("fma.rn.f32x2 %0, %1, %2, %3;" : "=l"(d) : "l"(a), "l"(b), "l"(d));
}

// zero guard regions (float guards for M, half guards for E)
__global__ __launch_bounds__(256) void k_zero_guards() {
    const int i = blockIdx.x * 256 + threadIdx.x;   // < GUARD/4 = 67584
    float4 z = make_float4(0.f, 0.f, 0.f, 0.f);
    ((float4 *)g_Mbuf)[i] = z;
    ((float4 *)(g_Mbuf + GUARD + NB * LL))[i] = z;
    if (i < GUARD / 8) {
        uint4 zu = make_uint4(0u, 0u, 0u, 0u);
        ((uint4 *)g_Eh)[i] = zu;
        ((uint4 *)(g_Eh + GUARD + NB * LL))[i] = zu;
    }
}

// ---- fp32 8-wide diagonal tap: reads M[(p+off)*L + (l+off)] for 8 l's ----
template <int DY, int DX>
__device__ __forceinline__ void tap8(const float *__restrict__ Mp, int l, float m,
                                     float eLo, float eHi, float *a) {
    constexpr int off = DY * 64 + DX;
    constexpr int offset = off * (L + 1);
    constexpr int r = offset & 3;
    const float *src = Mp + l + (offset - r);
    float f[12];
    float4 v0 = *(const float4 *)src;
    float4 v1 = *(const float4 *)(src + 4);
    f[0] = v0.x; f[1] = v0.y; f[2] = v0.z; f[3] = v0.w;
    f[4] = v1.x; f[5] = v1.y; f[6] = v1.z; f[7] = v1.w;
    if (r) {
        float4 v2 = *(const float4 *)(src + 8);
        f[8] = v2.x; f[9] = v2.y; f[10] = v2.z; f[11] = v2.w;
    }
    const float m0 = (DX == -1) ? m * eLo : m;
    const float m7 = (DX == 1) ? m * eHi : m;
    a[0] = fmaf(m0, f[r + 0], a[0]);
#pragma unroll
    for (int i = 1; i < 7; i++) a[i] = fmaf(m, f[r + i], a[i]);
    a[7] = fmaf(m7, f[r + 7], a[7]);
}

// ---- fp16 8-wide diagonal tap (E).  r = offset&7 is 0, 1 or 7. ----
template <int DY, int DX>
__device__ __forceinline__ void tap8h(const __half *__restrict__ Ep, int l, float m,
                                      float eLo, float eHi, float *a) {
    constexpr int off = DY * 64 + DX;
    constexpr int offset = off * (L + 1);
    constexpr int r = offset & 7;
    const __half *src = Ep + l + (offset - r);
    uint4 u0 = *(const uint4 *)src;
    unsigned pk[4];
    if (r == 0) {
        pk[0] = u0.x; pk[1] = u0.y; pk[2] = u0.z; pk[3] = u0.w;
    } else {
        uint4 u1 = *(const uint4 *)(src + 8);
        unsigned q[8] = {u0.x, u0.y, u0.z, u0.w, u1.x, u1.y, u1.z, u1.w};
        constexpr int base = (r - 1) / 2;
#pragma unroll
        for (int k = 0; k < 4; k++)
            pk[k] = __funnelshift_r(q[base + k], q[base + k + 1], 16);
    }
    float f[8];
#pragma unroll
    for (int k = 0; k < 4; k++) {
        float2 fv = __half22float2(*(const __half2 *)&pk[k]);
        f[2 * k] = fv.x;
        f[2 * k + 1] = fv.y;
    }
    const float m0 = (DX == -1) ? m * eLo : m;
    const float m7 = (DX == 1) ? m * eHi : m;
    a[0] = fmaf(m0, f[0], a[0]);
#pragma unroll
    for (int i = 1; i < 7; i++) a[i] = fmaf(m, f[i], a[i]);
    a[7] = fmaf(m7, f[7], a[7]);
}

// ============================================================
// K1: M[p,l] = sum_c f[c,p]*b[c,l]   128x128 tile, 8x8/thread
// ============================================================
__global__ __launch_bounds__(256) void k_gemm_M(const float *__restrict__ fin,
                                                const float *__restrict__ bin) {
    __shared__ float As[32][128];  // [c][p]
    __shared__ float Bs[32][128];  // [c][l]
    const int bt = blockIdx.z;
    const int p0 = blockIdx.y << 7;
    const int l0 = blockIdx.x << 7;
    const float *fb = fin + bt * (C * L);
    const float *bb = bin + bt * (C * L);
    const int tid = threadIdx.x;
    const int tx = tid & 15, ty = tid >> 4;
    unsigned long long acc[8][4] = {};

    for (int kt = 0; kt < 2; kt++) {
        __syncthreads();
#pragma unroll
        for (int i = 0; i < 4; i++) {
            int idx = tid + (i << 8);
            int c = idx >> 5, x4 = idx & 31;
            *(float4 *)&As[c][x4 << 2] =
                *(const float4 *)&fb[(kt * 32 + c) * L + p0 + (x4 << 2)];
            *(float4 *)&Bs[c][x4 << 2] =
                *(const float4 *)&bb[(kt * 32 + c) * L + l0 + (x4 << 2)];
        }
        __syncthreads();
#pragma unroll 8
        for (int c = 0; c < 32; c++) {
            float4 a0 = *(const float4 *)&As[c][ty << 3];
            float4 a1 = *(const float4 *)&As[c][(ty << 3) + 4];
            ulonglong2 b0 = *(const ulonglong2 *)&Bs[c][tx << 2];
            ulonglong2 b1 = *(const ulonglong2 *)&Bs[c][64 + (tx << 2)];
            unsigned long long ap[8];
            ap[0] = pack2(a0.x, a0.x); ap[1] = pack2(a0.y, a0.y);
            ap[2] = pack2(a0.z, a0.z); ap[3] = pack2(a0.w, a0.w);
            ap[4] = pack2(a1.x, a1.x); ap[5] = pack2(a1.y, a1.y);
            ap[6] = pack2(a1.z, a1.z); ap[7] = pack2(a1.w, a1.w);
#pragma unroll
            for (int i = 0; i < 8; i++) {
                fma2(acc[i][0], ap[i], b0.x);
                fma2(acc[i][1], ap[i], b0.y);
                fma2(acc[i][2], ap[i], b1.x);
                fma2(acc[i][3], ap[i], b1.y);
            }
        }
    }
    float *out = g_Mbuf + GUARD + (size_t)bt * LL;
#pragma unroll
    for (int i = 0; i < 8; i++) {
        const int row = p0 + (ty << 3) + i;
        ulonglong2 v0; v0.x = acc[i][0]; v0.y = acc[i][1];
        ulonglong2 v1; v1.x = acc[i][2]; v1.y = acc[i][3];
        *(ulonglong2 *)&out[row * L + l0 + (tx << 2)] = v0;
        *(ulonglong2 *)&out[row * L + l0 + 64 + (tx << 2)] = v1;
    }
}

// ============================================================
// K2: scores stencil (8-wide fp32 taps) + row softmax
// E = exp(10*(s-rowmax)) stored fp16; rinv stored separately.
// ============================================================
__global__ __launch_bounds__(256) void k_score_softmax() {
    const int bt = blockIdx.y;
    const int p = blockIdx.x;
    const int py = p >> 6, px = p & 63;
    const float *Mp = g_Mbuf + GUARD + (size_t)bt * LL + p * L;
    const int t = threadIdx.x;
    __shared__ float redA[8], redB[8];

    float pv[3][3];
#pragma unroll
    for (int dy = -1; dy <= 1; dy++)
#pragma unroll
        for (int dx = -1; dx <= 1; dx++)
            pv[dy + 1][dx + 1] =
                ((unsigned)(py + dy) < 64u && (unsigned)(px + dx) < 64u) ? 1.f : 0.f;
    const float eLo = ((t & 7) == 0) ? 0.f : 1.f;
    const float eHi = ((t & 7) == 7) ? 0.f : 1.f;

    float s[16];
#pragma unroll
    for (int j = 0; j < 2; j++) {
        const int gidx = (j << 8) + t;
        const int l = gidx << 3;
        const int ly = gidx >> 3;
        const float ym = ((unsigned)(ly - 1) < 64u) ? 1.f : 0.f;
        const float yp = ((unsigned)(ly + 1) < 64u) ? 1.f : 0.f;
        float a[8] = {};
        tap8<-1, -1>(Mp, l, pv[0][0] * ym, eLo, eHi, a);
        tap8<-1, 0>(Mp, l, pv[0][1] * ym, eLo, eHi, a);
        tap8<-1, 1>(Mp, l, pv[0][2] * ym, eLo, eHi, a);
        tap8<0, -1>(Mp, l, pv[1][0], eLo, eHi, a);
        tap8<0, 0>(Mp, l, pv[1][1], eLo, eHi, a);
        tap8<0, 1>(Mp, l, pv[1][2], eLo, eHi, a);
        tap8<1, -1>(Mp, l, pv[2][0] * yp, eLo, eHi, a);
        tap8<1, 0>(Mp, l, pv[2][1] * yp, eLo, eHi, a);
        tap8<1, 1>(Mp, l, pv[2][2] * yp, eLo, eHi, a);
#pragma unroll
        for (int i = 0; i < 8; i++) s[j * 8 + i] = a[i];
    }

    float m = s[0];
#pragma unroll
    for (int k = 1; k < 16; k++) m = fmaxf(m, s[k]);
#pragma unroll
    for (int o = 16; o; o >>= 1) m = fmaxf(m, __shfl_xor_sync(0xffffffffu, m, o));
    if ((t & 31) == 0) redA[t >> 5] = m;
    __syncthreads();
    float rowmax = redA[0];
#pragma unroll
    for (int i = 1; i < 8; i++) rowmax = fmaxf(rowmax, redA[i]);

    float sum = 0.f;
#pragma unroll
    for (int k = 0; k < 16; k++) {
        float e = __expf(10.f * (s[k] - rowmax));
        s[k] = e;
        sum += e;
    }
#pragma unroll
    for (int o = 16; o; o >>= 1) sum += __shfl_xor_sync(0xffffffffu, sum, o);
    if ((t & 31) == 0) redB[t >> 5] = sum;
    __syncthreads();

    __half *E = g_Eh + GUARD + (size_t)bt * LL + p * L;
#pragma unroll
    for (int j = 0; j < 2; j++) {
        const int l = ((j << 8) + t) << 3;
        __half2 h0 = __floats2half2_rn(s[j * 8 + 0], s[j * 8 + 1]);
        __half2 h1 = __floats2half2_rn(s[j * 8 + 2], s[j * 8 + 3]);
        __half2 h2 = __floats2half2_rn(s[j * 8 + 4], s[j * 8 + 5]);
        __half2 h3 = __floats2half2_rn(s[j * 8 + 6], s[j * 8 + 7]);
        uint4 u;
        u.x = *(unsigned *)&h0; u.y = *(unsigned *)&h1;
        u.z = *(unsigned *)&h2; u.w = *(unsigned *)&h3;
        *(uint4 *)&E[l] = u;
    }

    if (t == 0) {
        float tot = 0.f;
#pragma unroll
        for (int i = 0; i < 8; i++) tot += redB[i];
        g_rinv[bt][p] = 1.f / tot;
    }
}

// ============================================================
// K3: S[p,l] = (1/9) sum_d E[p+d,l+d]*rinv[p+d]  (E fp16 -> S fp32)
// ============================================================
__global__ __launch_bounds__(256) void k_attn_S() {
    const int bt = blockIdx.y;
    const int p = blockIdx.x;
    const int py = p >> 6, px = p & 63;
    const __half *Ep = g_Eh + GUARD + (size_t)bt * LL + p * L;
    const float *__restrict__ ri = g_rinv[bt];
    const int t = threadIdx.x;

    float rv[3][3];
#pragma unroll
    for (int dy = -1; dy <= 1; dy++)
#pragma unroll
        for (int dx = -1; dx <= 1; dx++) {
            bool ok = (unsigned)(py + dy) < 64u && (unsigned)(px + dx) < 64u;
            rv[dy + 1][dx + 1] = ok ? ri[p + dy * 64 + dx] : 0.f;
        }
    const float eLo = ((t & 7) == 0) ? 0.f : 1.f;
    const float eHi = ((t & 7) == 7) ? 0.f : 1.f;

    float *S = g_Mbuf + GUARD + (size_t)bt * LL + p * L;
#pragma unroll
    for (int j = 0; j < 2; j++) {
        const int gidx = (j << 8) + t;
        const int l = gidx << 3;
        const int ly = gidx >> 3;
        const float ym = ((unsigned)(ly - 1) < 64u) ? 1.f : 0.f;
        const float yp = ((unsigned)(ly + 1) < 64u) ? 1.f : 0.f;
        float a[8] = {};
        tap8h<-1, -1>(Ep, l, rv[0][0] * ym, eLo, eHi, a);
        tap8h<-1, 0>(Ep, l, rv[0][1] * ym, eLo, eHi, a);
        tap8h<-1, 1>(Ep, l, rv[0][2] * ym, eLo, eHi, a);
        tap8h<0, -1>(Ep, l, rv[1][0], eLo, eHi, a);
        tap8h<0, 0>(Ep, l, rv[1][1], eLo, eHi, a);
        tap8h<0, 1>(Ep, l, rv[1][2], eLo, eHi, a);
        tap8h<1, -1>(Ep, l, rv[2][0] * yp, eLo, eHi, a);
        tap8h<1, 0>(Ep, l, rv[2][1] * yp, eLo, eHi, a);
        tap8h<1, 1>(Ep, l, rv[2][2] * yp, eLo, eHi, a);
        *(float4 *)&S[l] = make_float4(a[0] * (1.f / 9.f), a[1] * (1.f / 9.f),
                                       a[2] * (1.f / 9.f), a[3] * (1.f / 9.f));
        *(float4 *)&S[l + 4] = make_float4(a[4] * (1.f / 9.f), a[5] * (1.f / 9.f),
                                           a[6] * (1.f / 9.f), a[7] * (1.f / 9.f));
    }
}

// ============================================================
// K4: split-K GEMM  y[c,p] = sum_l S[p,l]*b[c,l]
// grid (32 p-tiles, 8 k-splits, NB); 128 threads; 8x8/thread.
// ============================================================
__global__ __launch_bounds__(128) void k_gemm_y(const float *__restrict__ bin) {
    __shared__ float Ss[32][132];  // [l][p]
    __shared__ float Bt[32][68];   // [l][c]
    const int bt = blockIdx.z;
    const int ks = blockIdx.y;
    const int p0 = blockIdx.x << 7;
    const float *S = g_Mbuf + GUARD + (size_t)bt * LL;
    const float *bb = bin + bt * (C * L);
    const int tid = threadIdx.x;
    const int tx = tid & 15, ty = tid >> 4;  // tx->p(8), ty->c(8)
    unsigned long long acc[8][4] = {};

    const int lt_end = (ks + 1) << 9;
    for (int lt = ks << 9; lt < lt_end; lt += 32) {
        __syncthreads();
#pragma unroll
        for (int i = 0; i < 8; i++) {
            int idx = tid + (i << 7);
            int r = idx >> 3, q4 = idx & 7;
            float4 v = *(const float4 *)&S[(p0 + r) * L + lt + (q4 << 2)];
            Ss[(q4 << 2) + 0][r] = v.x;
            Ss[(q4 << 2) + 1][r] = v.y;
            Ss[(q4 << 2) + 2][r] = v.z;
            Ss[(q4 << 2) + 3][r] = v.w;
        }
#pragma unroll
        for (int i = 0; i < 4; i++) {
            int idx = tid + (i << 7);
            int r = idx >> 3, q4 = idx & 7;
            float4 v = *(const float4 *)&bb[r * L + lt + (q4 << 2)];
            Bt[(q4 << 2) + 0][r] = v.x;
            Bt[(q4 << 2) + 1][r] = v.y;
            Bt[(q4 << 2) + 2][r] = v.z;
            Bt[(q4 << 2) + 3][r] = v.w;
        }
        __syncthreads();
#pragma unroll 8
        for (int l = 0; l < 32; l++) {
            ulonglong2 s0 = *(const ulonglong2 *)&Ss[l][tx << 2];
            ulonglong2 s1 = *(const ulonglong2 *)&Ss[l][64 + (tx << 2)];
            float4 b0 = *(const float4 *)&Bt[l][ty << 3];
            float4 b1 = *(const float4 *)&Bt[l][(ty << 3) + 4];
            unsigned long long ap[8];
            ap[0] = pack2(b0.x, b0.x); ap[1] = pack2(b0.y, b0.y);
            ap[2] = pack2(b0.z, b0.z); ap[3] = pack2(b0.w, b0.w);
            ap[4] = pack2(b1.x, b1.x); ap[5] = pack2(b1.y, b1.y);
            ap[6] = pack2(b1.z, b1.z); ap[7] = pack2(b1.w, b1.w);
#pragma unroll
            for (int ci = 0; ci < 8; ci++) {
                fma2(acc[ci][0], ap[ci], s0.x);
                fma2(acc[ci][1], ap[ci], s0.y);
                fma2(acc[ci][2], ap[ci], s1.x);
                fma2(acc[ci][3], ap[ci], s1.y);
            }
        }
    }
#pragma unroll
    for (int ci = 0; ci < 8; ci++) {
        const int c = (ty << 3) + ci;
        float *dst = g_part + ((size_t)((bt << 3) + ks) * 64 + c) * L + p0;
        ulonglong2 v0; v0.x = acc[ci][0]; v0.y = acc[ci][1];
        ulonglong2 v1; v1.x = acc[ci][2]; v1.y = acc[ci][3];
        *(ulonglong2 *)(dst + (tx << 2)) = v0;
        *(ulonglong2 *)(dst + 64 + (tx << 2)) = v1;
    }
}

// reduce the 8 split-K partials into y
__global__ __launch_bounds__(256) void k_reduce_y(float *__restrict__ yout) {
    const int i = blockIdx.x * 256 + threadIdx.x;   // float4 idx, 262144 total
    const int p4 = i & 1023;
    const int c = (i >> 10) & 63;
    const int bt = i >> 16;
    const float4 *part = (const float4 *)g_part;
    float4 s = make_float4(0.f, 0.f, 0.f, 0.f);
#pragma unroll
    for (int ks = 0; ks < 8; ks++) {
        float4 v = part[((size_t)((bt << 3) + ks) * 64 + c) * 1024 + p4];
        s.x += v.x; s.y += v.y; s.z += v.z; s.w += v.w;
    }
    ((float4 *)yout)[(bt * 64 + c) * 1024 + p4] = s;
}

// ============================================================
// K5: w output: w[b,l,c,i,j] = b[c, l + (i-1,j-1)]  (0 when OOB)
// ============================================================
__global__ __launch_bounds__(256) void k_wout(const float *__restrict__ bin,
                                              float *__restrict__ wout) {
    const int idx = blockIdx.x * 256 + threadIdx.x;
    const int j3 = idx % 9;
    const int c = (idx / 9) & 63;
    const int l = (idx / 576) & 4095;
    const int bt = idx / (576 * 4096);
    const int dy = j3 / 3 - 1, dx = j3 % 3 - 1;
    const int ly = l >> 6, lx = l & 63;
    float v = 0.f;
    if ((unsigned)(ly + dy) < 64u && (unsigned)(lx + dx) < 64u)
        v = bin[bt * (C * L) + c * L + l + dy * 64 + dx];
    wout[idx] = v;
}

extern "C" void kernel_launch(void *const *d_in, const int *in_sizes, int n_in,
                              void *d_out, int out_size) {
    const float *f = (const float *)d_in[0];
    const float *b = (const float *)d_in[1];
    float *out = (float *)d_out;

    k_zero_guards<<<GUARD / 4 / 256, 256>>>();
    k_gemm_M<<<dim3(32, 32, NB), 256>>>(f, b);
    k_score_softmax<<<dim3(L, NB), 256>>>();
    k_attn_S<<<dim3(L, NB), 256>>>();
    k_gemm_y<<<dim3(32, 8, NB), 128>>>(b);
    k_reduce_y<<<1024, 256>>>(out);
    k_wout<<<(NB * L * C * 9) / 256, 256>>>(b, out + NB * C * L);
}

// round 10
// speedup vs baseline: 1.6543x; 1.2841x over previous
#include <cuda_runtime.h>
#include <cuda_fp16.h>

#define L 4096
#define C 64
#define NB 4
#define GUARD (66 * 4096)
#define LL (L * L)

// Guarded scratch for the stencils.
__device__ __align__(16) float  g_Mbuf[2 * GUARD + NB * LL];  // M (fp32)
__device__ __align__(16) __half g_Eh[2 * GUARD + NB * LL];    // E (fp16)
__device__ __align__(16) __half g_Sh[NB * LL];                // S (fp16)
__device__ __align__(16) __half g_bh[NB * C * L];             // b (fp16)
__device__ __align__(16) float  g_part[NB * 4 * C * L];       // split-K partials
__device__ float g_rinv[NB][L];

// ---- packed fp32x2 helpers ----
__device__ __forceinline__ unsigned long long pack2(float x, float y) {
    unsigned long long r;
    asm("mov.b64 %0, {%1, %2};" : "=l"(r) : "f"(x), "f"(y));
    return r;
}
__device__ __forceinline__ void fma2(unsigned long long &d, unsigned long long a,
                                     unsigned long long b) {
    asm("fma.rn.f32x2 %0, %1, %2, %3;" : "=l"(d) : "l"(a), "l"(b), "l"(d));
}

__global__ __launch_bounds__(256) void k_zero_guards() {
    const int i = blockIdx.x * 256 + threadIdx.x;   // < GUARD/4 = 67584
    float4 z = make_float4(0.f, 0.f, 0.f, 0.f);
    ((float4 *)g_Mbuf)[i] = z;
    ((float4 *)(g_Mbuf + GUARD + NB * LL))[i] = z;
    if (i < GUARD / 8) {
        uint4 zu = make_uint4(0u, 0u, 0u, 0u);
        ((uint4 *)g_Eh)[i] = zu;
        ((uint4 *)(g_Eh + GUARD + NB * LL))[i] = zu;
    }
}

// b -> fp16 (natural [c][l] layout)
__global__ __launch_bounds__(256) void k_prep_bh(const float *__restrict__ bin) {
    const int i = blockIdx.x * 256 + threadIdx.x;   // uint4 out idx, 131072 total
    const float4 *src = (const float4 *)bin;
    float4 v0 = src[2 * i], v1 = src[2 * i + 1];
    __half2 h0 = __floats2half2_rn(v0.x, v0.y);
    __half2 h1 = __floats2half2_rn(v0.z, v0.w);
    __half2 h2 = __floats2half2_rn(v1.x, v1.y);
    __half2 h3 = __floats2half2_rn(v1.z, v1.w);
    uint4 u;
    u.x = *(unsigned *)&h0; u.y = *(unsigned *)&h1;
    u.z = *(unsigned *)&h2; u.w = *(unsigned *)&h3;
    ((uint4 *)g_bh)[i] = u;
}

// ---- fp32 8-wide diagonal tap ----
template <int DY, int DX>
__device__ __forceinline__ void tap8(const float *__restrict__ Mp, int l, float m,
                                     float eLo, float eHi, float *a) {
    constexpr int off = DY * 64 + DX;
    constexpr int offset = off * (L + 1);
    constexpr int r = offset & 3;
    const float *src = Mp + l + (offset - r);
    float f[12];
    float4 v0 = *(const float4 *)src;
    float4 v1 = *(const float4 *)(src + 4);
    f[0] = v0.x; f[1] = v0.y; f[2] = v0.z; f[3] = v0.w;
    f[4] = v1.x; f[5] = v1.y; f[6] = v1.z; f[7] = v1.w;
    if (r) {
        float4 v2 = *(const float4 *)(src + 8);
        f[8] = v2.x; f[9] = v2.y; f[10] = v2.z; f[11] = v2.w;
    }
    const float m0 = (DX == -1) ? m * eLo : m;
    const float m7 = (DX == 1) ? m * eHi : m;
    a[0] = fmaf(m0, f[r + 0], a[0]);
#pragma unroll
    for (int i = 1; i < 7; i++) a[i] = fmaf(m, f[r + i], a[i]);
    a[7] = fmaf(m7, f[r + 7], a[7]);
}

// ---- fp16 8-wide diagonal tap (E) ----
template <int DY, int DX>
__device__ __forceinline__ void tap8h(const __half *__restrict__ Ep, int l, float m,
                                      float eLo, float eHi, float *a) {
    constexpr int off = DY * 64 + DX;
    constexpr int offset = off * (L + 1);
    constexpr int r = offset & 7;
    const __half *src = Ep + l + (offset - r);
    uint4 u0 = *(const uint4 *)src;
    unsigned pk[4];
    if (r == 0) {
        pk[0] = u0.x; pk[1] = u0.y; pk[2] = u0.z; pk[3] = u0.w;
    } else {
        uint4 u1 = *(const uint4 *)(src + 8);
        unsigned q[8] = {u0.x, u0.y, u0.z, u0.w, u1.x, u1.y, u1.z, u1.w};
        constexpr int base = (r - 1) / 2;
#pragma unroll
        for (int k = 0; k < 4; k++)
            pk[k] = __funnelshift_r(q[base + k], q[base + k + 1], 16);
    }
    float f[8];
#pragma unroll
    for (int k = 0; k < 4; k++) {
        float2 fv = __half22float2(*(const __half2 *)&pk[k]);
        f[2 * k] = fv.x;
        f[2 * k + 1] = fv.y;
    }
    const float m0 = (DX == -1) ? m * eLo : m;
    const float m7 = (DX == 1) ? m * eHi : m;
    a[0] = fmaf(m0, f[0], a[0]);
#pragma unroll
    for (int i = 1; i < 7; i++) a[i] = fmaf(m, f[i], a[i]);
    a[7] = fmaf(m7, f[7], a[7]);
}

// ============================================================
// K1: M[p,l] = sum_c f[c,p]*b[c,l]   128x128 tile, 8x8/thread (SIMT)
// ============================================================
__global__ __launch_bounds__(256) void k_gemm_M(const float *__restrict__ fin,
                                                const float *__restrict__ bin) {
    __shared__ float As[32][128];
    __shared__ float Bs[32][128];
    const int bt = blockIdx.z;
    const int p0 = blockIdx.y << 7;
    const int l0 = blockIdx.x << 7;
    const float *fb = fin + bt * (C * L);
    const float *bb = bin + bt * (C * L);
    const int tid = threadIdx.x;
    const int tx = tid & 15, ty = tid >> 4;
    unsigned long long acc[8][4] = {};

    for (int kt = 0; kt < 2; kt++) {
        __syncthreads();
#pragma unroll
        for (int i = 0; i < 4; i++) {
            int idx = tid + (i << 8);
            int c = idx >> 5, x4 = idx & 31;
            *(float4 *)&As[c][x4 << 2] =
                *(const float4 *)&fb[(kt * 32 + c) * L + p0 + (x4 << 2)];
            *(float4 *)&Bs[c][x4 << 2] =
                *(const float4 *)&bb[(kt * 32 + c) * L + l0 + (x4 << 2)];
        }
        __syncthreads();
#pragma unroll 8
        for (int c = 0; c < 32; c++) {
            float4 a0 = *(const float4 *)&As[c][ty << 3];
            float4 a1 = *(const float4 *)&As[c][(ty << 3) + 4];
            ulonglong2 b0 = *(const ulonglong2 *)&Bs[c][tx << 2];
            ulonglong2 b1 = *(const ulonglong2 *)&Bs[c][64 + (tx << 2)];
            unsigned long long ap[8];
            ap[0] = pack2(a0.x, a0.x); ap[1] = pack2(a0.y, a0.y);
            ap[2] = pack2(a0.z, a0.z); ap[3] = pack2(a0.w, a0.w);
            ap[4] = pack2(a1.x, a1.x); ap[5] = pack2(a1.y, a1.y);
            ap[6] = pack2(a1.z, a1.z); ap[7] = pack2(a1.w, a1.w);
#pragma unroll
            for (int i = 0; i < 8; i++) {
                fma2(acc[i][0], ap[i], b0.x);
                fma2(acc[i][1], ap[i], b0.y);
                fma2(acc[i][2], ap[i], b1.x);
                fma2(acc[i][3], ap[i], b1.y);
            }
        }
    }
    float *out = g_Mbuf + GUARD + (size_t)bt * LL;
#pragma unroll
    for (int i = 0; i < 8; i++) {
        const int row = p0 + (ty << 3) + i;
        ulonglong2 v0; v0.x = acc[i][0]; v0.y = acc[i][1];
        ulonglong2 v1; v1.x = acc[i][2]; v1.y = acc[i][3];
        *(ulonglong2 *)&out[row * L + l0 + (tx << 2)] = v0;
        *(ulonglong2 *)&out[row * L + l0 + 64 + (tx << 2)] = v1;
    }
}

// ============================================================
// K2: scores stencil + softmax; E stored fp16
// ============================================================
__global__ __launch_bounds__(256) void k_score_softmax() {
    const int bt = blockIdx.y;
    const int p = blockIdx.x;
    const int py = p >> 6, px = p & 63;
    const float *Mp = g_Mbuf + GUARD + (size_t)bt * LL + p * L;
    const int t = threadIdx.x;
    __shared__ float redA[8], redB[8];

    float pv[3][3];
#pragma unroll
    for (int dy = -1; dy <= 1; dy++)
#pragma unroll
        for (int dx = -1; dx <= 1; dx++)
            pv[dy + 1][dx + 1] =
                ((unsigned)(py + dy) < 64u && (unsigned)(px + dx) < 64u) ? 1.f : 0.f;
    const float eLo = ((t & 7) == 0) ? 0.f : 1.f;
    const float eHi = ((t & 7) == 7) ? 0.f : 1.f;

    float s[16];
#pragma unroll
    for (int j = 0; j < 2; j++) {
        const int gidx = (j << 8) + t;
        const int l = gidx << 3;
        const int ly = gidx >> 3;
        const float ym = ((unsigned)(ly - 1) < 64u) ? 1.f : 0.f;
        const float yp = ((unsigned)(ly + 1) < 64u) ? 1.f : 0.f;
        float a[8] = {};
        tap8<-1, -1>(Mp, l, pv[0][0] * ym, eLo, eHi, a);
        tap8<-1, 0>(Mp, l, pv[0][1] * ym, eLo, eHi, a);
        tap8<-1, 1>(Mp, l, pv[0][2] * ym, eLo, eHi, a);
        tap8<0, -1>(Mp, l, pv[1][0], eLo, eHi, a);
        tap8<0, 0>(Mp, l, pv[1][1], eLo, eHi, a);
        tap8<0, 1>(Mp, l, pv[1][2], eLo, eHi, a);
        tap8<1, -1>(Mp, l, pv[2][0] * yp, eLo, eHi, a);
        tap8<1, 0>(Mp, l, pv[2][1] * yp, eLo, eHi, a);
        tap8<1, 1>(Mp, l, pv[2][2] * yp, eLo, eHi, a);
#pragma unroll
        for (int i = 0; i < 8; i++) s[j * 8 + i] = a[i];
    }

    float m = s[0];
#pragma unroll
    for (int k = 1; k < 16; k++) m = fmaxf(m, s[k]);
#pragma unroll
    for (int o = 16; o; o >>= 1) m = fmaxf(m, __shfl_xor_sync(0xffffffffu, m, o));
    if ((t & 31) == 0) redA[t >> 5] = m;
    __syncthreads();
    float rowmax = redA[0];
#pragma unroll
    for (int i = 1; i < 8; i++) rowmax = fmaxf(rowmax, redA[i]);

    float sum = 0.f;
#pragma unroll
    for (int k = 0; k < 16; k++) {
        float e = __expf(10.f * (s[k] - rowmax));
        s[k] = e;
        sum += e;
    }
#pragma unroll
    for (int o = 16; o; o >>= 1) sum += __shfl_xor_sync(0xffffffffu, sum, o);
    if ((t & 31) == 0) redB[t >> 5] = sum;
    __syncthreads();

    __half *E = g_Eh + GUARD + (size_t)bt * LL + p * L;
#pragma unroll
    for (int j = 0; j < 2; j++) {
        const int l = ((j << 8) + t) << 3;
        __half2 h0 = __floats2half2_rn(s[j * 8 + 0], s[j * 8 + 1]);
        __half2 h1 = __floats2half2_rn(s[j * 8 + 2], s[j * 8 + 3]);
        __half2 h2 = __floats2half2_rn(s[j * 8 + 4], s[j * 8 + 5]);
        __half2 h3 = __floats2half2_rn(s[j * 8 + 6], s[j * 8 + 7]);
        uint4 u;
        u.x = *(unsigned *)&h0; u.y = *(unsigned *)&h1;
        u.z = *(unsigned *)&h2; u.w = *(unsigned *)&h3;
        *(uint4 *)&E[l] = u;
    }

    if (t == 0) {
        float tot = 0.f;
#pragma unroll
        for (int i = 0; i < 8; i++) tot += redB[i];
        g_rinv[bt][p] = 1.f / tot;
    }
}

// ============================================================
// K3: S = (1/9) stencil(E * rinv)  (E fp16 -> S fp16)
// ============================================================
__global__ __launch_bounds__(256) void k_attn_S() {
    const int bt = blockIdx.y;
    const int p = blockIdx.x;
    const int py = p >> 6, px = p & 63;
    const __half *Ep = g_Eh + GUARD + (size_t)bt * LL + p * L;
    const float *__restrict__ ri = g_rinv[bt];
    const int t = threadIdx.x;

    float rv[3][3];
#pragma unroll
    for (int dy = -1; dy <= 1; dy++)
#pragma unroll
        for (int dx = -1; dx <= 1; dx++) {
            bool ok = (unsigned)(py + dy) < 64u && (unsigned)(px + dx) < 64u;
            rv[dy + 1][dx + 1] = ok ? ri[p + dy * 64 + dx] : 0.f;
        }
    const float eLo = ((t & 7) == 0) ? 0.f : 1.f;
    const float eHi = ((t & 7) == 7) ? 0.f : 1.f;

    __half *S = g_Sh + (size_t)bt * LL + p * L;
#pragma unroll
    for (int j = 0; j < 2; j++) {
        const int gidx = (j << 8) + t;
        const int l = gidx << 3;
        const int ly = gidx >> 3;
        const float ym = ((unsigned)(ly - 1) < 64u) ? 1.f : 0.f;
        const float yp = ((unsigned)(ly + 1) < 64u) ? 1.f : 0.f;
        float a[8] = {};
        tap8h<-1, -1>(Ep, l, rv[0][0] * ym, eLo, eHi, a);
        tap8h<-1, 0>(Ep, l, rv[0][1] * ym, eLo, eHi, a);
        tap8h<-1, 1>(Ep, l, rv[0][2] * ym, eLo, eHi, a);
        tap8h<0, -1>(Ep, l, rv[1][0], eLo, eHi, a);
        tap8h<0, 0>(Ep, l, rv[1][1], eLo, eHi, a);
        tap8h<0, 1>(Ep, l, rv[1][2], eLo, eHi, a);
        tap8h<1, -1>(Ep, l, rv[2][0] * yp, eLo, eHi, a);
        tap8h<1, 0>(Ep, l, rv[2][1] * yp, eLo, eHi, a);
        tap8h<1, 1>(Ep, l, rv[2][2] * yp, eLo, eHi, a);
        __half2 h0 = __floats2half2_rn(a[0] * (1.f / 9.f), a[1] * (1.f / 9.f));
        __half2 h1 = __floats2half2_rn(a[2] * (1.f / 9.f), a[3] * (1.f / 9.f));
        __half2 h2 = __floats2half2_rn(a[4] * (1.f / 9.f), a[5] * (1.f / 9.f));
        __half2 h3 = __floats2half2_rn(a[6] * (1.f / 9.f), a[7] * (1.f / 9.f));
        uint4 u;
        u.x = *(unsigned *)&h0; u.y = *(unsigned *)&h1;
        u.z = *(unsigned *)&h2; u.w = *(unsigned *)&h3;
        *(uint4 *)&S[l] = u;
    }
}

// ============================================================
// K4 (tensor): y[c,p] = sum_l b[c,l]*S[p,l]
// Block: c=64 x p=128 tile, K split x4 (1024 l each), 128 threads.
// A = b fp16 [c][l] row-major;  B = S fp16 [p][l] = [n][k] row-major,
// which IS the mma col-major B fragment layout -> ldmatrix WITHOUT trans.
// ============================================================
__global__ __launch_bounds__(128) void k_gemm_y_mma() {
    __shared__ __half As[64 * 64];    // b tile  [c][l64]  swizzled
    __shared__ __half Bs[128 * 64];   // S tile  [p][l64]  swizzled
    const int bt = blockIdx.z;
    const int ks = blockIdx.y;
    const int p0 = blockIdx.x << 7;
    const int tid = threadIdx.x;
    const int warp = tid >> 5, lane = tid & 31;
    const __half *bh = g_bh + bt * (C * L);
    const __half *Sb = g_Sh + (size_t)bt * LL;

    unsigned asB = (unsigned)__cvta_generic_to_shared(As);
    unsigned bsB = (unsigned)__cvta_generic_to_shared(Bs);

    float acc[16][4];
#pragma unroll
    for (int j = 0; j < 16; j++)
#pragma unroll
        for (int k = 0; k < 4; k++) acc[j][k] = 0.f;

    const int aRow = warp * 16 + (lane & 15);
    const int aSel = lane >> 4;
    const int bRowBase = ((lane >> 4) << 3) + (lane & 7);
    const int bSel = (lane >> 3) & 1;
    const int swz = lane & 7;

    const int lt0 = ks << 10;
    for (int lt = lt0; lt < lt0 + 1024; lt += 64) {
        __syncthreads();
#pragma unroll
        for (int i = 0; i < 4; i++) {
            int idx = tid + (i << 7);
            int row = idx >> 3, g = idx & 7;
            *(uint4 *)&As[row * 64 + ((g ^ (row & 7)) << 3)] =
                *(const uint4 *)&bh[row * L + lt + (g << 3)];
        }
#pragma unroll
        for (int i = 0; i < 8; i++) {
            int idx = tid + (i << 7);
            int row = idx >> 3, g = idx & 7;
            *(uint4 *)&Bs[row * 64 + ((g ^ (row & 7)) << 3)] =
                *(const uint4 *)&Sb[(size_t)(p0 + row) * L + lt + (g << 3)];
        }
        __syncthreads();
#pragma unroll
        for (int k8 = 0; k8 < 4; k8++) {
            unsigned a0, a1, a2, a3;
            {
                int phys = ((k8 << 1) + aSel) ^ (aRow & 7);
                unsigned addr = asB + aRow * 128 + (phys << 4);
                asm volatile(
                    "ldmatrix.sync.aligned.m8n8.x4.shared.b16 {%0,%1,%2,%3}, [%4];"
                    : "=r"(a0), "=r"(a1), "=r"(a2), "=r"(a3) : "r"(addr));
            }
            const int bPhys = ((k8 << 1) + bSel) ^ swz;
#pragma unroll
            for (int jp = 0; jp < 8; jp++) {
                unsigned b0, b1, b2, b3;
                unsigned addr = bsB + (jp * 16 + bRowBase) * 128 + (bPhys << 4);
                asm volatile(
                    "ldmatrix.sync.aligned.m8n8.x4.shared.b16 {%0,%1,%2,%3}, [%4];"
                    : "=r"(b0), "=r"(b1), "=r"(b2), "=r"(b3) : "r"(addr));
                float *d0 = acc[2 * jp];
                float *d1 = acc[2 * jp + 1];
                asm volatile(
                    "mma.sync.aligned.m16n8k16.row.col.f32.f16.f16.f32 "
                    "{%0,%1,%2,%3}, {%4,%5,%6,%7}, {%8,%9}, {%0,%1,%2,%3};"
                    : "+f"(d0[0]), "+f"(d0[1]), "+f"(d0[2]), "+f"(d0[3])
                    : "r"(a0), "r"(a1), "r"(a2), "r"(a3), "r"(b0), "r"(b1));
                asm volatile(
                    "mma.sync.aligned.m16n8k16.row.col.f32.f16.f16.f32 "
                    "{%0,%1,%2,%3}, {%4,%5,%6,%7}, {%8,%9}, {%0,%1,%2,%3};"
                    : "+f"(d1[0]), "+f"(d1[1]), "+f"(d1[2]), "+f"(d1[3])
                    : "r"(a0), "r"(a1), "r"(a2), "r"(a3), "r"(b2), "r"(b3));
            }
        }
    }
    float *part = g_part + (size_t)((bt << 2) + ks) * (C * L);
    const int cRow = warp * 16 + (lane >> 2);
#pragma unroll
    for (int j = 0; j < 16; j++) {
        const int pc = p0 + j * 8 + ((lane & 3) << 1);
        float2 v0; v0.x = acc[j][0]; v0.y = acc[j][1];
        float2 v1; v1.x = acc[j][2]; v1.y = acc[j][3];
        *(float2 *)&part[cRow * L + pc] = v0;
        *(float2 *)&part[(cRow + 8) * L + pc] = v1;
    }
}

// reduce the 4 split-K partials into y
__global__ __launch_bounds__(256) void k_reduce_y(float *__restrict__ yout) {
    const int i = blockIdx.x * 256 + threadIdx.x;   // float4 idx, 262144 total
    const int p4 = i & 1023;
    const int c = (i >> 10) & 63;
    const int bt = i >> 16;
    const float4 *part = (const float4 *)g_part;
    float4 s = make_float4(0.f, 0.f, 0.f, 0.f);
#pragma unroll
    for (int ks = 0; ks < 4; ks++) {
        float4 v = part[((size_t)((bt << 2) + ks) * 64 + c) * 1024 + p4];
        s.x += v.x; s.y += v.y; s.z += v.z; s.w += v.w;
    }
    ((float4 *)yout)[(bt * 64 + c) * 1024 + p4] = s;
}

// ============================================================
// K5: w output
// ============================================================
__global__ __launch_bounds__(256) void k_wout(const float *__restrict__ bin,
                                              float *__restrict__ wout) {
    const int idx = blockIdx.x * 256 + threadIdx.x;
    const int j3 = idx % 9;
    const int c = (idx / 9) & 63;
    const int l = (idx / 576) & 4095;
    const int bt = idx / (576 * 4096);
    const int dy = j3 / 3 - 1, dx = j3 % 3 - 1;
    const int ly = l >> 6, lx = l & 63;
    float v = 0.f;
    if ((unsigned)(ly + dy) < 64u && (unsigned)(lx + dx) < 64u)
        v = bin[bt * (C * L) + c * L + l + dy * 64 + dx];
    wout[idx] = v;
}

extern "C" void kernel_launch(void *const *d_in, const int *in_sizes, int n_in,
                              void *d_out, int out_size) {
    const float *f = (const float *)d_in[0];
    const float *b = (const float *)d_in[1];
    float *out = (float *)d_out;

    k_zero_guards<<<GUARD / 4 / 256, 256>>>();
    k_prep_bh<<<512, 256>>>(b);
    k_gemm_M<<<dim3(32, 32, NB), 256>>>(f, b);
    k_score_softmax<<<dim3(L, NB), 256>>>();
    k_attn_S<<<dim3(L, NB), 256>>>();
    k_gemm_y_mma<<<dim3(32, 4, NB), 128>>>();
    k_reduce_y<<<1024, 256>>>(out);
    k_wout<<<(NB * L * C * 9) / 256, 256>>>(b, out + NB * C * L);
}

// round 12
// speedup vs baseline: 1.9049x; 1.1515x over previous
#include <cuda_runtime.h>
#include <cuda_fp16.h>

#define L 4096
#define C 64
#define NB 4
#define GUARD (66 * 4096)
#define LL (L * L)

// Guarded scratch for the stencils.
__device__ __align__(16) float  g_Mbuf[2 * GUARD + NB * LL];  // M (fp32)
__device__ __align__(16) __half g_Eh[2 * GUARD + NB * LL];    // E (fp16)
__device__ __align__(16) __half g_Sh[NB * LL];                // S (fp16)
__device__ __align__(16) __half g_bh[NB * C * L];             // b (fp16, [c][l])
__device__ __align__(16) __half g_fth[NB * L * C];            // f^T hi [x][c]
__device__ __align__(16) __half g_ftl[NB * L * C];            // f^T lo
__device__ __align__(16) __half g_bth[NB * L * C];            // b^T hi [x][c]
__device__ __align__(16) __half g_btl[NB * L * C];            // b^T lo
__device__ __align__(16) float  g_part[NB * 4 * C * L];       // split-K partials
__device__ float g_rinv[NB][L];

__global__ __launch_bounds__(256) void k_zero_guards() {
    const int i = blockIdx.x * 256 + threadIdx.x;   // < GUARD/4 = 67584
    float4 z = make_float4(0.f, 0.f, 0.f, 0.f);
    ((float4 *)g_Mbuf)[i] = z;
    ((float4 *)(g_Mbuf + GUARD + NB * LL))[i] = z;
    if (i < GUARD / 8) {
        uint4 zu = make_uint4(0u, 0u, 0u, 0u);
        ((uint4 *)g_Eh)[i] = zu;
        ((uint4 *)(g_Eh + GUARD + NB * LL))[i] = zu;
    }
}

// b -> fp16 (natural [c][l] layout, for K4)
__global__ __launch_bounds__(256) void k_prep_bh(const float *__restrict__ bin) {
    const int i = blockIdx.x * 256 + threadIdx.x;   // uint4 out idx, 131072 total
    const float4 *src = (const float4 *)bin;
    float4 v0 = src[2 * i], v1 = src[2 * i + 1];
    __half2 h0 = __floats2half2_rn(v0.x, v0.y);
    __half2 h1 = __floats2half2_rn(v0.z, v0.w);
    __half2 h2 = __floats2half2_rn(v1.x, v1.y);
    __half2 h3 = __floats2half2_rn(v1.z, v1.w);
    uint4 u;
    u.x = *(unsigned *)&h0; u.y = *(unsigned *)&h1;
    u.z = *(unsigned *)&h2; u.w = *(unsigned *)&h3;
    ((uint4 *)g_bh)[i] = u;
}

// f,b -> transposed [x][c] fp16 hi/lo split (for K1 MMA)
__global__ __launch_bounds__(256) void k_prep_split(const float *__restrict__ fin,
                                                    const float *__restrict__ bin) {
    __shared__ float tile[64][72];
    const int bt = blockIdx.y;
    const int x0 = blockIdx.x << 6;
    const int z = blockIdx.z;
    const float *src = (z ? bin : fin) + bt * (C * L);
    __half *dh = (z ? g_bth : g_fth) + ((size_t)bt * L + x0) * 64;
    __half *dl = (z ? g_btl : g_ftl) + ((size_t)bt * L + x0) * 64;
    const int tid = threadIdx.x;
#pragma unroll
    for (int i = 0; i < 4; i++) {
        int idx = tid + (i << 8);          // 1024 float4 loads
        int c = idx >> 4, x4 = idx & 15;
        *(float4 *)&tile[c][x4 << 2] =
            *(const float4 *)&src[c * L + x0 + (x4 << 2)];
    }
    __syncthreads();
#pragma unroll
    for (int i = 0; i < 2; i++) {
        int idx = tid + (i << 8);          // 512 output uint4 pairs
        int xr = idx >> 3, g = idx & 7;
        __half hs[8], ls[8];
#pragma unroll
        for (int j = 0; j < 8; j++) {
            float v = tile[(g << 3) + j][xr];
            __half h = __float2half_rn(v);
            hs[j] = h;
            ls[j] = __float2half_rn(v - __half2float(h));
        }
        *(uint4 *)&dh[xr * 64 + (g << 3)] = *(uint4 *)hs;
        *(uint4 *)&dl[xr * 64 + (g << 3)] = *(uint4 *)ls;
    }
}

// ---- fp32 8-wide diagonal tap ----
template <int DY, int DX>
__device__ __forceinline__ void tap8(const float *__restrict__ Mp, int l, float m,
                                     float eLo, float eHi, float *a) {
    constexpr int off = DY * 64 + DX;
    constexpr int offset = off * (L + 1);
    constexpr int r = offset & 3;
    const float *src = Mp + l + (offset - r);
    float f[12];
    float4 v0 = *(const float4 *)src;
    float4 v1 = *(const float4 *)(src + 4);
    f[0] = v0.x; f[1] = v0.y; f[2] = v0.z; f[3] = v0.w;
    f[4] = v1.x; f[5] = v1.y; f[6] = v1.z; f[7] = v1.w;
    if (r) {
        float4 v2 = *(const float4 *)(src + 8);
        f[8] = v2.x; f[9] = v2.y; f[10] = v2.z; f[11] = v2.w;
    }
    const float m0 = (DX == -1) ? m * eLo : m;
    const float m7 = (DX == 1) ? m * eHi : m;
    a[0] = fmaf(m0, f[r + 0], a[0]);
#pragma unroll
    for (int i = 1; i < 7; i++) a[i] = fmaf(m, f[r + i], a[i]);
    a[7] = fmaf(m7, f[r + 7], a[7]);
}

// ---- fp16 8-wide diagonal tap (E) ----
template <int DY, int DX>
__device__ __forceinline__ void tap8h(const __half *__restrict__ Ep, int l, float m,
                                      float eLo, float eHi, float *a) {
    constexpr int off = DY * 64 + DX;
    constexpr int offset = off * (L + 1);
    constexpr int r = offset & 7;
    const __half *src = Ep + l + (offset - r);
    uint4 u0 = *(const uint4 *)src;
    unsigned pk[4];
    if (r == 0) {
        pk[0] = u0.x; pk[1] = u0.y; pk[2] = u0.z; pk[3] = u0.w;
    } else {
        uint4 u1 = *(const uint4 *)(src + 8);
        unsigned q[8] = {u0.x, u0.y, u0.z, u0.w, u1.x, u1.y, u1.z, u1.w};
        constexpr int base = (r - 1) / 2;
#pragma unroll
        for (int k = 0; k < 4; k++)
            pk[k] = __funnelshift_r(q[base + k], q[base + k + 1], 16);
    }
    float f[8];
#pragma unroll
    for (int k = 0; k < 4; k++) {
        float2 fv = __half22float2(*(const __half2 *)&pk[k]);
        f[2 * k] = fv.x;
        f[2 * k + 1] = fv.y;
    }
    const float m0 = (DX == -1) ? m * eLo : m;
    const float m7 = (DX == 1) ? m * eHi : m;
    a[0] = fmaf(m0, f[0], a[0]);
#pragma unroll
    for (int i = 1; i < 7; i++) a[i] = fmaf(m, f[i], a[i]);
    a[7] = fmaf(m7, f[7], a[7]);
}

// ---- shared MMA micro-pass: one (A,B) smem pair, K=64, warp 64x32 tile ----
__device__ __forceinline__ void mma_pass(unsigned aBase, unsigned bBase,
                                         int warpP, int warpL, int lane,
                                         float acc[4][4][4]) {
    const int aRowL = lane & 15, aSel = lane >> 4;
    const int bRowBase = ((lane >> 4) << 3) + (lane & 7);
    const int bSel = (lane >> 3) & 1, swz = lane & 7;
#pragma unroll
    for (int k8 = 0; k8 < 4; k8++) {
        unsigned a[4][4];
#pragma unroll
        for (int mi = 0; mi < 4; mi++) {
            int row = warpP + (mi << 4) + aRowL;
            int phys = ((k8 << 1) + aSel) ^ (row & 7);
            unsigned addr = aBase + row * 128 + (phys << 4);
            asm volatile(
                "ldmatrix.sync.aligned.m8n8.x4.shared.b16 {%0,%1,%2,%3}, [%4];"
                : "=r"(a[mi][0]), "=r"(a[mi][1]), "=r"(a[mi][2]), "=r"(a[mi][3])
                : "r"(addr));
        }
        const int bPhys = ((k8 << 1) + bSel) ^ swz;
#pragma unroll
        for (int jp = 0; jp < 2; jp++) {
            unsigned b0, b1, b2, b3;
            unsigned addr = bBase + (warpL + (jp << 4) + bRowBase) * 128 + (bPhys << 4);
            asm volatile(
                "ldmatrix.sync.aligned.m8n8.x4.shared.b16 {%0,%1,%2,%3}, [%4];"
                : "=r"(b0), "=r"(b1), "=r"(b2), "=r"(b3) : "r"(addr));
#pragma unroll
            for (int mi = 0; mi < 4; mi++) {
                float *d0 = acc[mi][2 * jp];
                float *d1 = acc[mi][2 * jp + 1];
                asm volatile(
                    "mma.sync.aligned.m16n8k16.row.col.f32.f16.f16.f32 "
                    "{%0,%1,%2,%3}, {%4,%5,%6,%7}, {%8,%9}, {%0,%1,%2,%3};"
                    : "+f"(d0[0]), "+f"(d0[1]), "+f"(d0[2]), "+f"(d0[3])
                    : "r"(a[mi][0]), "r"(a[mi][1]), "r"(a[mi][2]), "r"(a[mi][3]),
                      "r"(b0), "r"(b1));
                asm volatile(
                    "mma.sync.aligned.m16n8k16.row.col.f32.f16.f16.f32 "
                    "{%0,%1,%2,%3}, {%4,%5,%6,%7}, {%8,%9}, {%0,%1,%2,%3};"
                    : "+f"(d1[0]), "+f"(d1[1]), "+f"(d1[2]), "+f"(d1[3])
                    : "r"(a[mi][0]), "r"(a[mi][1]), "r"(a[mi][2]), "r"(a[mi][3]),
                      "r"(b2), "r"(b3));
            }
        }
    }
}

// ============================================================
// K1 (tensor): M[p,l] = sum_c f[c,p]*b[c,l] with hi/lo fp16 split:
// M = fh*bh + fl*bh + fh*bl   (fl*bl dropped, ~1e-7 rel)
// Block: 128p x 128l, K=64 all in smem.  8 warps = 2(p) x 4(l).
// ============================================================
__global__ __launch_bounds__(256) void k_gemm_M_mma() {
    __shared__ __half Ah[128 * 64];
    __shared__ __half Al[128 * 64];
    __shared__ __half Bs[128 * 64];
    const int bt = blockIdx.z;
    const int p0 = blockIdx.y << 7;
    const int l0 = blockIdx.x << 7;
    const int tid = threadIdx.x;
    const int warp = tid >> 5, lane = tid & 31;
    const int warpP = (warp >> 2) << 6;   // 0 / 64
    const int warpL = (warp & 3) << 5;    // 0,32,64,96
    const __half *fh = g_fth + ((size_t)bt * L + p0) * 64;
    const __half *fl = g_ftl + ((size_t)bt * L + p0) * 64;
    const __half *bh = g_bth + ((size_t)bt * L + l0) * 64;
    const __half *bl = g_btl + ((size_t)bt * L + l0) * 64;

    unsigned aB = (unsigned)__cvta_generic_to_shared(Ah);
    unsigned lB = (unsigned)__cvta_generic_to_shared(Al);
    unsigned bB = (unsigned)__cvta_generic_to_shared(Bs);

    float acc[4][4][4];
#pragma unroll
    for (int i = 0; i < 4; i++)
#pragma unroll
        for (int j = 0; j < 4; j++)
#pragma unroll
            for (int k = 0; k < 4; k++) acc[i][j][k] = 0.f;

#pragma unroll
    for (int i = 0; i < 4; i++) {
        int idx = tid + (i << 8);          // 1024 uint4 per tile
        int row = idx >> 3, g = idx & 7;
        int soff = row * 64 + ((g ^ (row & 7)) << 3);
        *(uint4 *)&Ah[soff] = *(const uint4 *)&fh[row * 64 + (g << 3)];
        *(uint4 *)&Al[soff] = *(const uint4 *)&fl[row * 64 + (g << 3)];
        *(uint4 *)&Bs[soff] = *(const uint4 *)&bh[row * 64 + (g << 3)];
    }
    __syncthreads();
    mma_pass(aB, bB, warpP, warpL, lane, acc);   // fh * bh
    mma_pass(lB, bB, warpP, warpL, lane, acc);   // fl * bh
    __syncthreads();
#pragma unroll
    for (int i = 0; i < 4; i++) {
        int idx = tid + (i << 8);
        int row = idx >> 3, g = idx & 7;
        *(uint4 *)&Bs[row * 64 + ((g ^ (row & 7)) << 3)] =
            *(const uint4 *)&bl[row * 64 + (g << 3)];
    }
    __syncthreads();
    mma_pass(aB, bB, warpP, warpL, lane, acc);   // fh * bl

    float *out = g_Mbuf + GUARD + (size_t)bt * LL;
    const int mRow = lane >> 2, nCol = (lane & 3) << 1;
#pragma unroll
    for (int mi = 0; mi < 4; mi++) {
        const int r = p0 + warpP + (mi << 4) + mRow;
#pragma unroll
        for (int n8 = 0; n8 < 4; n8++) {
            const int cc = l0 + warpL + (n8 << 3) + nCol;
            float2 v0; v0.x = acc[mi][n8][0]; v0.y = acc[mi][n8][1];
            float2 v1; v1.x = acc[mi][n8][2]; v1.y = acc[mi][n8][3];
            *(float2 *)&out[(size_t)r * L + cc] = v0;
            *(float2 *)&out[(size_t)(r + 8) * L + cc] = v1;
        }
    }
}

// ============================================================
// K2: scores stencil + softmax; E stored fp16
// ============================================================
__global__ __launch_bounds__(256) void k_score_softmax() {
    const int bt = blockIdx.y;
    const int p = blockIdx.x;
    const int py = p >> 6, px = p & 63;
    const float *Mp = g_Mbuf + GUARD + (size_t)bt * LL + p * L;
    const int t = threadIdx.x;
    __shared__ float redA[8], redB[8];

    float pv[3][3];
#pragma unroll
    for (int dy = -1; dy <= 1; dy++)
#pragma unroll
        for (int dx = -1; dx <= 1; dx++)
            pv[dy + 1][dx + 1] =
                ((unsigned)(py + dy) < 64u && (unsigned)(px + dx) < 64u) ? 1.f : 0.f;
    const float eLo = ((t & 7) == 0) ? 0.f : 1.f;
    const float eHi = ((t & 7) == 7) ? 0.f : 1.f;

    float s[16];
#pragma unroll
    for (int j = 0; j < 2; j++) {
        const int gidx = (j << 8) + t;
        const int l = gidx << 3;
        const int ly = gidx >> 3;
        const float ym = ((unsigned)(ly - 1) < 64u) ? 1.f : 0.f;
        const float yp = ((unsigned)(ly + 1) < 64u) ? 1.f : 0.f;
        float a[8] = {};
        tap8<-1, -1>(Mp, l, pv[0][0] * ym, eLo, eHi, a);
        tap8<-1, 0>(Mp, l, pv[0][1] * ym, eLo, eHi, a);
        tap8<-1, 1>(Mp, l, pv[0][2] * ym, eLo, eHi, a);
        tap8<0, -1>(Mp, l, pv[1][0], eLo, eHi, a);
        tap8<0, 0>(Mp, l, pv[1][1], eLo, eHi, a);
        tap8<0, 1>(Mp, l, pv[1][2], eLo, eHi, a);
        tap8<1, -1>(Mp, l, pv[2][0] * yp, eLo, eHi, a);
        tap8<1, 0>(Mp, l, pv[2][1] * yp, eLo, eHi, a);
        tap8<1, 1>(Mp, l, pv[2][2] * yp, eLo, eHi, a);
#pragma unroll
        for (int i = 0; i < 8; i++) s[j * 8 + i] = a[i];
    }

    float m = s[0];
#pragma unroll
    for (int k = 1; k < 16; k++) m = fmaxf(m, s[k]);
#pragma unroll
    for (int o = 16; o; o >>= 1) m = fmaxf(m, __shfl_xor_sync(0xffffffffu, m, o));
    if ((t & 31) == 0) redA[t >> 5] = m;
    __syncthreads();
    float rowmax = redA[0];
#pragma unroll
    for (int i = 1; i < 8; i++) rowmax = fmaxf(rowmax, redA[i]);

    float sum = 0.f;
#pragma unroll
    for (int k = 0; k < 16; k++) {
        float e = __expf(10.f * (s[k] - rowmax));
        s[k] = e;
        sum += e;
    }
#pragma unroll
    for (int o = 16; o; o >>= 1) sum += __shfl_xor_sync(0xffffffffu, sum, o);
    if ((t & 31) == 0) redB[t >> 5] = sum;
    __syncthreads();

    __half *E = g_Eh + GUARD + (size_t)bt * LL + p * L;
#pragma unroll
    for (int j = 0; j < 2; j++) {
        const int l = ((j << 8) + t) << 3;
        __half2 h0 = __floats2half2_rn(s[j * 8 + 0], s[j * 8 + 1]);
        __half2 h1 = __floats2half2_rn(s[j * 8 + 2], s[j * 8 + 3]);
        __half2 h2 = __floats2half2_rn(s[j * 8 + 4], s[j * 8 + 5]);
        __half2 h3 = __floats2half2_rn(s[j * 8 + 6], s[j * 8 + 7]);
        uint4 u;
        u.x = *(unsigned *)&h0; u.y = *(unsigned *)&h1;
        u.z = *(unsigned *)&h2; u.w = *(unsigned *)&h3;
        *(uint4 *)&E[l] = u;
    }

    if (t == 0) {
        float tot = 0.f;
#pragma unroll
        for (int i = 0; i < 8; i++) tot += redB[i];
        g_rinv[bt][p] = 1.f / tot;
    }
}

// ============================================================
// K3: S = (1/9) stencil(E * rinv)  (E fp16 -> S fp16)
// ============================================================
__global__ __launch_bounds__(256) void k_attn_S() {
    const int bt = blockIdx.y;
    const int p = blockIdx.x;
    const int py = p >> 6, px = p & 63;
    const __half *Ep = g_Eh + GUARD + (size_t)bt * LL + p * L;
    const float *__restrict__ ri = g_rinv[bt];
    const int t = threadIdx.x;

    float rv[3][3];
#pragma unroll
    for (int dy = -1; dy <= 1; dy++)
#pragma unroll
        for (int dx = -1; dx <= 1; dx++) {
            bool ok = (unsigned)(py + dy) < 64u && (unsigned)(px + dx) < 64u;
            rv[dy + 1][dx + 1] = ok ? ri[p + dy * 64 + dx] : 0.f;
        }
    const float eLo = ((t & 7) == 0) ? 0.f : 1.f;
    const float eHi = ((t & 7) == 7) ? 0.f : 1.f;

    __half *S = g_Sh + (size_t)bt * LL + p * L;
#pragma unroll
    for (int j = 0; j < 2; j++) {
        const int gidx = (j << 8) + t;
        const int l = gidx << 3;
        const int ly = gidx >> 3;
        const float ym = ((unsigned)(ly - 1) < 64u) ? 1.f : 0.f;
        const float yp = ((unsigned)(ly + 1) < 64u) ? 1.f : 0.f;
        float a[8] = {};
        tap8h<-1, -1>(Ep, l, rv[0][0] * ym, eLo, eHi, a);
        tap8h<-1, 0>(Ep, l, rv[0][1] * ym, eLo, eHi, a);
        tap8h<-1, 1>(Ep, l, rv[0][2] * ym, eLo, eHi, a);
        tap8h<0, -1>(Ep, l, rv[1][0], eLo, eHi, a);
        tap8h<0, 0>(Ep, l, rv[1][1], eLo, eHi, a);
        tap8h<0, 1>(Ep, l, rv[1][2], eLo, eHi, a);
        tap8h<1, -1>(Ep, l, rv[2][0] * yp, eLo, eHi, a);
        tap8h<1, 0>(Ep, l, rv[2][1] * yp, eLo, eHi, a);
        tap8h<1, 1>(Ep, l, rv[2][2] * yp, eLo, eHi, a);
        __half2 h0 = __floats2half2_rn(a[0] * (1.f / 9.f), a[1] * (1.f / 9.f));
        __half2 h1 = __floats2half2_rn(a[2] * (1.f / 9.f), a[3] * (1.f / 9.f));
        __half2 h2 = __floats2half2_rn(a[4] * (1.f / 9.f), a[5] * (1.f / 9.f));
        __half2 h3 = __floats2half2_rn(a[6] * (1.f / 9.f), a[7] * (1.f / 9.f));
        uint4 u;
        u.x = *(unsigned *)&h0; u.y = *(unsigned *)&h1;
        u.z = *(unsigned *)&h2; u.w = *(unsigned *)&h3;
        *(uint4 *)&S[l] = u;
    }
}

// ============================================================
// K4 (tensor): y[c,p] = sum_l b[c,l]*S[p,l]
// ============================================================
__global__ __launch_bounds__(128) void k_gemm_y_mma() {
    __shared__ __half As[64 * 64];
    __shared__ __half Bs[128 * 64];
    const int bt = blockIdx.z;
    const int ks = blockIdx.y;
    const int p0 = blockIdx.x << 7;
    const int tid = threadIdx.x;
    const int warp = tid >> 5, lane = tid & 31;
    const __half *bh = g_bh + bt * (C * L);
    const __half *Sb = g_Sh + (size_t)bt * LL;

    unsigned asB = (unsigned)__cvta_generic_to_shared(As);
    unsigned bsB = (unsigned)__cvta_generic_to_shared(Bs);

    float acc[16][4];
#pragma unroll
    for (int j = 0; j < 16; j++)
#pragma unroll
        for (int k = 0; k < 4; k++) acc[j][k] = 0.f;

    const int aRow = warp * 16 + (lane & 15);
    const int aSel = lane >> 4;
    const int bRowBase = ((lane >> 4) << 3) + (lane & 7);
    const int bSel = (lane >> 3) & 1;
    const int swz = lane & 7;

    const int lt0 = ks << 10;
    for (int lt = lt0; lt < lt0 + 1024; lt += 64) {
        __syncthreads();
#pragma unroll
        for (int i = 0; i < 4; i++) {
            int idx = tid + (i << 7);
            int row = idx >> 3, g = idx & 7;
            *(uint4 *)&As[row * 64 + ((g ^ (row & 7)) << 3)] =
                *(const uint4 *)&bh[row * L + lt + (g << 3)];
        }
#pragma unroll
        for (int i = 0; i < 8; i++) {
            int idx = tid + (i << 7);
            int row = idx >> 3, g = idx & 7;
            *(uint4 *)&Bs[row * 64 + ((g ^ (row & 7)) << 3)] =
                *(const uint4 *)&Sb[(size_t)(p0 + row) * L + lt + (g << 3)];
        }
        __syncthreads();
#pragma unroll
        for (int k8 = 0; k8 < 4; k8++) {
            unsigned a0, a1, a2, a3;
            {
                int phys = ((k8 << 1) + aSel) ^ (aRow & 7);
                unsigned addr = asB + aRow * 128 + (phys << 4);
                asm volatile(
                    "ldmatrix.sync.aligned.m8n8.x4.shared.b16 {%0,%1,%2,%3}, [%4];"
                    : "=r"(a0), "=r"(a1), "=r"(a2), "=r"(a3) : "r"(addr));
            }
            const int bPhys = ((k8 << 1) + bSel) ^ swz;
#pragma unroll
            for (int jp = 0; jp < 8; jp++) {
                unsigned b0, b1, b2, b3;
                unsigned addr = bsB + (jp * 16 + bRowBase) * 128 + (bPhys << 4);
                asm volatile(
                    "ldmatrix.sync.aligned.m8n8.x4.shared.b16 {%0,%1,%2,%3}, [%4];"
                    : "=r"(b0), "=r"(b1), "=r"(b2), "=r"(b3) : "r"(addr));
                float *d0 = acc[2 * jp];
                float *d1 = acc[2 * jp + 1];
                asm volatile(
                    "mma.sync.aligned.m16n8k16.row.col.f32.f16.f16.f32 "
                    "{%0,%1,%2,%3}, {%4,%5,%6,%7}, {%8,%9}, {%0,%1,%2,%3};"
                    : "+f"(d0[0]), "+f"(d0[1]), "+f"(d0[2]), "+f"(d0[3])
                    : "r"(a0), "r"(a1), "r"(a2), "r"(a3), "r"(b0), "r"(b1));
                asm volatile(
                    "mma.sync.aligned.m16n8k16.row.col.f32.f16.f16.f32 "
                    "{%0,%1,%2,%3}, {%4,%5,%6,%7}, {%8,%9}, {%0,%1,%2,%3};"
                    : "+f"(d1[0]), "+f"(d1[1]), "+f"(d1[2]), "+f"(d1[3])
                    : "r"(a0), "r"(a1), "r"(a2), "r"(a3), "r"(b2), "r"(b3));
            }
        }
    }
    float *part = g_part + (size_t)((bt << 2) + ks) * (C * L);
    const int cRow = warp * 16 + (lane >> 2);
#pragma unroll
    for (int j = 0; j < 16; j++) {
        const int pc = p0 + j * 8 + ((lane & 3) << 1);
        float2 v0; v0.x = acc[j][0]; v0.y = acc[j][1];
        float2 v1; v1.x = acc[j][2]; v1.y = acc[j][3];
        *(float2 *)&part[cRow * L + pc] = v0;
        *(float2 *)&part[(cRow + 8) * L + pc] = v1;
    }
}

// reduce the 4 split-K partials into y
__global__ __launch_bounds__(256) void k_reduce_y(float *__restrict__ yout) {
    const int i = blockIdx.x * 256 + threadIdx.x;   // float4 idx, 262144 total
    const int p4 = i & 1023;
    const int c = (i >> 10) & 63;
    const int bt = i >> 16;
    const float4 *part = (const float4 *)g_part;
    float4 s = make_float4(0.f, 0.f, 0.f, 0.f);
#pragma unroll
    for (int ks = 0; ks < 4; ks++) {
        float4 v = part[((size_t)((bt << 2) + ks) * 64 + c) * 1024 + p4];
        s.x += v.x; s.y += v.y; s.z += v.z; s.w += v.w;
    }
    ((float4 *)yout)[(bt * 64 + c) * 1024 + p4] = s;
}

// ============================================================
// K5: w output
// ============================================================
__global__ __launch_bounds__(256) void k_wout(const float *__restrict__ bin,
                                              float *__restrict__ wout) {
    const int idx = blockIdx.x * 256 + threadIdx.x;
    const int j3 = idx % 9;
    const int c = (idx / 9) & 63;
    const int l = (idx / 576) & 4095;
    const int bt = idx / (576 * 4096);
    const int dy = j3 / 3 - 1, dx = j3 % 3 - 1;
    const int ly = l >> 6, lx = l & 63;
    float v = 0.f;
    if ((unsigned)(ly + dy) < 64u && (unsigned)(lx + dx) < 64u)
        v = bin[bt * (C * L) + c * L + l + dy * 64 + dx];
    wout[idx] = v;
}

extern "C" void kernel_launch(void *const *d_in, const int *in_sizes, int n_in,
                              void *d_out, int out_size) {
    const float *f = (const float *)d_in[0];
    const float *b = (const float *)d_in[1];
    float *out = (float *)d_out;

    k_zero_guards<<<GUARD / 4 / 256, 256>>>();
    k_prep_bh<<<512, 256>>>(b);
    k_prep_split<<<dim3(64, NB, 2), 256>>>(f, b);
    k_gemm_M_mma<<<dim3(32, 32, NB), 256>>>();
    k_score_softmax<<<dim3(L, NB), 256>>>();
    k_attn_S<<<dim3(L, NB), 256>>>();
    k_gemm_y_mma<<<dim3(32, 4, NB), 128>>>();
    k_reduce_y<<<1024, 256>>>(out);
    k_wout<<<(NB * L * C * 9) / 256, 256>>>(b, out + NB * C * L);
}